// round 13
// baseline (speedup 1.0000x reference)
#include <cuda_runtime.h>
#include <cuda_fp16.h>
#include <cstdint>

// ---------------- problem constants ----------------
#define BB 2
#define TT 2048
#define DD 1024
#define HH 16
#define KK 4
#define HD 64
#define CONV (3*DD)
#define MM (BB*TT)          // 4096 tokens
#define CH 16               // staged scan chunk
#define NCH (TT / CH)

// ---------------- device scratch ----------------
__device__ float g_mixed[(size_t)MM * CONV];
__device__ float g_act[(size_t)MM * CONV];
__device__ float g_z[(size_t)MM * DD];
__device__ float g_att[(size_t)MM * 2 * HH];
__device__ float g_eg[(size_t)MM * HH];
__device__ float g_o[(size_t)MM * DD];
// fp16 pre-converted GEMM operands
__device__ __half g_xh[(size_t)MM * DD];
__device__ __half g_wqh[(size_t)CONV * DD];
__device__ __half g_wzh[(size_t)DD * DD];
__device__ __half g_woh[(size_t)DD * DD];
__device__ __half g_oh[(size_t)MM * DD];

__device__ __forceinline__ uint32_t smem_u32(const void* p) {
    uint32_t a;
    asm("{ .reg .u64 t; cvta.to.shared.u64 t, %1; cvt.u32.u64 %0, t; }" : "=r"(a) : "l"(p));
    return a;
}

#define LDSM_X4(r0, r1, r2, r3, addr)                                            \
    asm volatile("ldmatrix.sync.aligned.m8n8.x4.shared.b16 {%0,%1,%2,%3}, [%4];" \
                 : "=r"(r0), "=r"(r1), "=r"(r2), "=r"(r3) : "r"(addr))

// ---------------- fused fp16 cvt pre-pass (all 4 operands, 1 launch) ----------------
#define CV0 (MM * DD / 4)
#define CV1 (CONV * DD / 4)
#define CV2 (DD * DD / 4)
#define CVTOT (CV0 + CV1 + 2 * CV2)

__global__ __launch_bounds__(256) void cvt_all_kernel(const float4* __restrict__ x,
                                                      const float4* __restrict__ wq,
                                                      const float4* __restrict__ wz,
                                                      const float4* __restrict__ wo,
                                                      uint2* __restrict__ xh,
                                                      uint2* __restrict__ wqh,
                                                      uint2* __restrict__ wzh,
                                                      uint2* __restrict__ woh) {
    int i = blockIdx.x * 256 + threadIdx.x;
    const float4* src;
    uint2* dst;
    int off;
    if (i < CV0)                  { src = x;  dst = xh;  off = i; }
    else if (i < CV0 + CV1)       { src = wq; dst = wqh; off = i - CV0; }
    else if (i < CV0 + CV1 + CV2) { src = wz; dst = wzh; off = i - CV0 - CV1; }
    else                          { src = wo; dst = woh; off = i - CV0 - CV1 - CV2; }
    float4 v = src[off];
    __half2 lo = __floats2half2_rn(v.x, v.y);
    __half2 hi = __floats2half2_rn(v.z, v.w);
    dst[off] = make_uint2(*(uint32_t*)&lo, *(uint32_t*)&hi);
}

// ---------------- fp16 tensor-core GEMM: C[M,N] = A[M,K] @ W[N,K]^T ----------------
// 256 threads = 8 warps (2x4), block 128x128x64, warp tile 64x32.
// ldmatrix fragment loads; GBK=64 halves sync count. Double-buffered dynamic smem.
#define GBK 64
#define KPH 36                    // pair stride per row (32 + 4 pad)
#define TILEW (128 * KPH)         // 4608 words
#define BUFW (2 * TILEW)          // A + B per buffer
#define GSMEM (2 * BUFW * 4)      // 73728 bytes

__global__ __launch_bounds__(256) void hgemm_nt(const __half* __restrict__ A,
                                                const __half* __restrict__ W,
                                                float* __restrict__ C,
                                                int M, int N, int Kd) {
    extern __shared__ uint32_t sm[];
    int tid = threadIdx.x;
    int wid = tid >> 5;
    int lane = tid & 31;
    int bm = blockIdx.y * 128;
    int bn = blockIdx.x * 128;
    int wm = (wid & 1) * 64;
    int wn = (wid >> 1) * 32;
    int g = lane >> 2;
    int tg = lane & 3;

    uint32_t smbase = smem_u32(sm);
    // staging: 2 threads per row; each covers 64B (4 x 16B) of the 128B row
    int srow = tid >> 1;                // 0..127
    int shalf = tid & 1;
    const __half* Ap = A + (size_t)(bm + srow) * Kd + shalf * 32;
    const __half* Wp = W + (size_t)(bn + srow) * Kd + shalf * 32;
    uint32_t rowoff = srow * (KPH * 4) + shalf * 64;

    // ldmatrix per-lane base addresses (buffer 0)
    int lr = lane & 7;
    int lh = (lane >> 3) & 1;
    int lq = lane >> 4;
    uint32_t aBase[4];
#pragma unroll
    for (int mi = 0; mi < 4; mi++)
        aBase[mi] = smbase + (uint32_t)(wm + mi * 16 + lr + lh * 8) * (KPH * 4) + lq * 16;
    uint32_t bBase[2];
#pragma unroll
    for (int p = 0; p < 2; p++)
        bBase[p] = smbase + TILEW * 4 +
                   (uint32_t)(wn + p * 16 + lq * 8 + lr) * (KPH * 4) + lh * 16;

    float acc[4][4][4];
#pragma unroll
    for (int i = 0; i < 4; i++)
#pragma unroll
        for (int j = 0; j < 4; j++)
#pragma unroll
            for (int c = 0; c < 4; c++) acc[i][j][c] = 0.f;

#define STAGE(itx)                                                               \
    {                                                                            \
        uint32_t boff = smbase + ((itx) & 1) * (BUFW * 4) + rowoff;              \
        int ko = (itx) * GBK;                                                    \
        _Pragma("unroll")                                                        \
        for (int c = 0; c < 4; c++) {                                            \
            asm volatile("cp.async.cg.shared.global [%0], [%1], 16;"             \
                         :: "r"(boff + c * 16), "l"(Ap + ko + c * 8));           \
            asm volatile("cp.async.cg.shared.global [%0], [%1], 16;"             \
                         :: "r"(boff + TILEW * 4 + c * 16), "l"(Wp + ko + c * 8)); \
        }                                                                        \
        asm volatile("cp.async.commit_group;");                                  \
    }

    STAGE(0);

    int ntile = Kd / GBK;               // 16
    for (int it = 0; it < ntile; it++) {
        bool more = (it + 1) < ntile;
        if (more) STAGE(it + 1);
        if (more) asm volatile("cp.async.wait_group 1;");
        else      asm volatile("cp.async.wait_group 0;");
        __syncthreads();

        uint32_t bsel = (uint32_t)(it & 1) * (BUFW * 4);

#pragma unroll
        for (int ks = 0; ks < 4; ks++) {
            uint32_t kofs = bsel + ks * 32;
            uint32_t af[4][4];
            uint32_t bb[2][4];
#pragma unroll
            for (int mi = 0; mi < 4; mi++)
                LDSM_X4(af[mi][0], af[mi][1], af[mi][2], af[mi][3], aBase[mi] + kofs);
#pragma unroll
            for (int p = 0; p < 2; p++)
                LDSM_X4(bb[p][0], bb[p][1], bb[p][2], bb[p][3], bBase[p] + kofs);

#pragma unroll
            for (int mi = 0; mi < 4; mi++)
#pragma unroll
                for (int ni = 0; ni < 4; ni++) {
                    uint32_t b0 = bb[ni >> 1][(ni & 1) * 2];
                    uint32_t b1 = bb[ni >> 1][(ni & 1) * 2 + 1];
                    asm volatile(
                        "mma.sync.aligned.m16n8k16.row.col.f32.f16.f16.f32 "
                        "{%0,%1,%2,%3}, {%4,%5,%6,%7}, {%8,%9}, {%0,%1,%2,%3};"
                        : "+f"(acc[mi][ni][0]), "+f"(acc[mi][ni][1]),
                          "+f"(acc[mi][ni][2]), "+f"(acc[mi][ni][3])
                        : "r"(af[mi][0]), "r"(af[mi][1]), "r"(af[mi][2]), "r"(af[mi][3]),
                          "r"(b0), "r"(b1));
                }
        }
        __syncthreads();
    }
#undef STAGE

#pragma unroll
    for (int mi = 0; mi < 4; mi++) {
#pragma unroll
        for (int ni = 0; ni < 4; ni++) {
            int row0 = bm + wm + mi * 16 + g;
            int col = bn + wn + ni * 8 + tg * 2;
            *(float2*)(C + (size_t)row0 * N + col) =
                make_float2(acc[mi][ni][0], acc[mi][ni][1]);
            *(float2*)(C + (size_t)(row0 + 8) * N + col) =
                make_float2(acc[mi][ni][2], acc[mi][ni][3]);
        }
    }
}

// ---------------- beta/g raw projections, 8 tokens per block ----------------
__global__ __launch_bounds__(256) void att_kernel(const float* __restrict__ x,
                                                  const float* __restrict__ Wb,
                                                  const float* __restrict__ Wa,
                                                  float* __restrict__ att) {
    __shared__ float xs[8][DD];
    int m0 = blockIdx.x * 8;
    int tid = threadIdx.x;
#pragma unroll
    for (int r = 0; r < 8; r++)
        *(float4*)&xs[r][tid * 4] = *(const float4*)(x + (size_t)(m0 + r) * DD + tid * 4);
    __syncthreads();

    int g = tid >> 3;
    int sub = tid & 7;
    const float* w = (g < HH) ? (Wb + (size_t)g * DD) : (Wa + (size_t)(g - HH) * DD);
    float s[8];
#pragma unroll
    for (int r = 0; r < 8; r++) s[r] = 0.f;

    for (int j = sub * 4; j < DD; j += 32) {
        float4 wv = *(const float4*)(w + j);
#pragma unroll
        for (int r = 0; r < 8; r++) {
            float4 xv = *(const float4*)(&xs[r][j]);
            s[r] += wv.x * xv.x + wv.y * xv.y + wv.z * xv.z + wv.w * xv.w;
        }
    }
#pragma unroll
    for (int r = 0; r < 8; r++) {
        s[r] += __shfl_xor_sync(0xffffffffu, s[r], 4);
        s[r] += __shfl_xor_sync(0xffffffffu, s[r], 2);
        s[r] += __shfl_xor_sync(0xffffffffu, s[r], 1);
        if (sub == 0) att[(size_t)(m0 + r) * 32 + g] = s[r];
    }
}

// ---------------- FUSED: causal conv(K=4) + SiLU + l2norm q/k + v*beta + eg ----------------
// One warp per (m,h); lane covers channels {lane, lane+32} of q, k, v.
// Identical arithmetic order to the previous conv_silu + prep pipeline.
__global__ __launch_bounds__(128) void conv_prep_kernel(const float* __restrict__ mixed,
                                                        const float* __restrict__ cw,
                                                        const float* __restrict__ att,
                                                        const float* __restrict__ dt_bias,
                                                        const float* __restrict__ A_log,
                                                        float* __restrict__ act,
                                                        float* __restrict__ eg) {
    int w = blockIdx.x * 4 + (threadIdx.x >> 5);
    int lane = threadIdx.x & 31;
    int m = w >> 4;
    int h = w & (HH - 1);
    int t = m & (TT - 1);
    int c0 = h * HD + lane;

    float out[6];
#pragma unroll
    for (int s = 0; s < 6; s++) {
        int ch = (s >> 1) * DD + c0 + (s & 1) * 32;
        float4 wv = *(const float4*)(cw + (size_t)ch * KK);
        const float* wp = (const float*)&wv;
        float a = 0.f;
#pragma unroll
        for (int j = 0; j < KK; j++) {
            if (t - 3 + j >= 0)
                a += wp[j] * __ldg(mixed + (size_t)(m - 3 + j) * CONV + ch);
        }
        out[s] = a / (1.f + expf(-a));
    }

    // q l2norm (* HD^-0.5)
    float sq = out[0] * out[0] + out[1] * out[1];
#pragma unroll
    for (int o = 16; o; o >>= 1) sq += __shfl_xor_sync(0xffffffffu, sq, o);
    float invq = rsqrtf(sq + 1e-6f) * 0.125f;

    // k l2norm
    float sk = out[2] * out[2] + out[3] * out[3];
#pragma unroll
    for (int o = 16; o; o >>= 1) sk += __shfl_xor_sync(0xffffffffu, sk, o);
    float invk = rsqrtf(sk + 1e-6f);

    // beta, g
    float bdot = att[(size_t)m * 32 + h];
    float adot = att[(size_t)m * 32 + HH + h];
    float beta = 1.f / (1.f + expf(-bdot));
    float spin = adot + dt_bias[h];
    float sp = (spin > 20.f) ? spin : log1pf(expf(spin));
    float gg = -expf(A_log[h]) * sp;

    float* base = act + (size_t)m * CONV + h * HD;
    base[lane]           = out[0] * invq;
    base[lane + 32]      = out[1] * invq;
    base[DD + lane]      = out[2] * invk;
    base[DD + lane + 32] = out[3] * invk;
    base[2 * DD + lane]      = out[4] * beta;
    base[2 * DD + lane + 32] = out[5] * beta;
    if (lane == 0) eg[(size_t)m * HH + h] = expf(gg);
}

// ---------------- sequential gated scan, smem chunk-staged, batched shuffles ----------------
// grid 256 = 32 (b,h) * 8 col-groups ; 64 threads.
__global__ __launch_bounds__(64) void scan_kernel(const float* __restrict__ act,
                                                  const float* __restrict__ eg,
                                                  float* __restrict__ o) {
    __shared__ float sq[2][CH][64];
    __shared__ float sk[2][CH][64];
    __shared__ float sv[2][CH][8];
    __shared__ float se[2][CH];

    int bh = blockIdx.x >> 3;
    int cg = blockIdx.x & 7;
    int b = bh >> 4;
    int h = bh & (HH - 1);
    int tid = threadIdx.x;
    int vloc = tid >> 3;
    int part = tid & 7;
    int dbase = part * 8;
    int col = cg * 8 + vloc;

    float S[8];
#pragma unroll
    for (int i = 0; i < 8; i++) S[i] = 0.f;

    const float* abase = act + (size_t)b * TT * CONV + h * HD;
    const float* ebase = eg + (size_t)b * TT * HH + h;
    float* obase = o + (size_t)b * TT * DD + h * HD + col;

    int srow = tid >> 2;
    int sq4 = (tid & 3) * 16;
    uint32_t aq = smem_u32(&sq[0][0][0]);
    uint32_t ak = smem_u32(&sk[0][0][0]);
    uint32_t av = smem_u32(&sv[0][0][0]);
    uint32_t ae = smem_u32(&se[0][0]);

#define SSTAGE(cx)                                                                \
    {                                                                             \
        int bufx = (cx) & 1;                                                      \
        int t0 = (cx) * CH;                                                       \
        const float* gq = abase + (size_t)(t0 + srow) * CONV + sq4;               \
        const float* gk = gq + DD;                                                \
        uint32_t dq = aq + (bufx * CH * 64 + srow * 64 + sq4) * 4;                \
        uint32_t dk = ak + (bufx * CH * 64 + srow * 64 + sq4) * 4;                \
        _Pragma("unroll")                                                         \
        for (int j = 0; j < 4; j++) {                                             \
            asm volatile("cp.async.cg.shared.global [%0], [%1], 16;"              \
                         :: "r"(dq + j * 16), "l"(gq + j * 4));                   \
            asm volatile("cp.async.cg.shared.global [%0], [%1], 16;"              \
                         :: "r"(dk + j * 16), "l"(gk + j * 4));                   \
        }                                                                         \
        if (tid < 32) {                                                           \
            int tv = tid >> 1;                                                    \
            int c2 = (tid & 1) * 4;                                               \
            const float* gv = abase + (size_t)(t0 + tv) * CONV + 2 * DD           \
                              + cg * 8 + c2;                                      \
            uint32_t dv = av + (bufx * CH * 8 + tv * 8 + c2) * 4;                 \
            asm volatile("cp.async.ca.shared.global [%0], [%1], 16;"              \
                         :: "r"(dv), "l"(gv));                                    \
        }                                                                         \
        if (tid < 16) {                                                           \
            const float* ge = ebase + (size_t)(t0 + tid) * HH;                    \
            uint32_t de = ae + (bufx * CH + tid) * 4;                             \
            asm volatile("cp.async.ca.shared.global [%0], [%1], 4;"               \
                         :: "r"(de), "l"(ge));                                    \
        }                                                                         \
        asm volatile("cp.async.commit_group;");                                   \
    }

    SSTAGE(0);

    for (int c = 0; c < NCH; c++) {
        bool more = (c + 1) < NCH;
        if (more) SSTAGE(c + 1);
        if (more) asm volatile("cp.async.wait_group 1;");
        else      asm volatile("cp.async.wait_group 0;");
        __syncthreads();

        int buf = c & 1;
        float dots[CH];
#pragma unroll
        for (int tt = 0; tt < CH; tt++) {
            float qq[8], kk[8];
            *(float4*)(qq + 0) = *(const float4*)(&sq[buf][tt][dbase]);
            *(float4*)(qq + 4) = *(const float4*)(&sq[buf][tt][dbase + 4]);
            *(float4*)(kk + 0) = *(const float4*)(&sk[buf][tt][dbase]);
            *(float4*)(kk + 4) = *(const float4*)(&sk[buf][tt][dbase + 4]);
            float v = sv[buf][tt][vloc];
            float e = se[buf][tt];
            float dot = 0.f;
#pragma unroll
            for (int i = 0; i < 8; i++) {
                S[i] = S[i] * e + kk[i] * v;
                dot += qq[i] * S[i];
            }
            dots[tt] = dot;
        }
#pragma unroll
        for (int tt = 0; tt < CH; tt++) {
            float d = dots[tt];
            d += __shfl_xor_sync(0xffffffffu, d, 1);
            d += __shfl_xor_sync(0xffffffffu, d, 2);
            d += __shfl_xor_sync(0xffffffffu, d, 4);
            if (part == 0) obase[(size_t)(c * CH + tt) * DD] = d;
        }
        __syncthreads();
    }
#undef SSTAGE
}

// ---------------- gated RMSNorm over head dim -> fp16 for final projection ----------------
__global__ __launch_bounds__(128) void post_kernel(const float* __restrict__ o,
                                                   const float* __restrict__ z,
                                                   __half* __restrict__ oh) {
    int w = blockIdx.x * 4 + (threadIdx.x >> 5);
    int lane = threadIdx.x & 31;
    int m = w >> 4;
    int h = w & (HH - 1);
    const float* ob = o + (size_t)m * DD + h * HD;
    const float* zb = z + (size_t)m * DD + h * HD;
    __half* oo = oh + (size_t)m * DD + h * HD;

    float o0 = ob[lane], o1 = ob[lane + 32];
    float s = o0 * o0 + o1 * o1;
#pragma unroll
    for (int off = 16; off; off >>= 1) s += __shfl_xor_sync(0xffffffffu, s, off);
    float r = rsqrtf(s * (1.f / 64.f) + 1e-6f);

    float z0 = zb[lane], z1 = zb[lane + 32];
    float g0 = z0 / (1.f + expf(-z0));
    float g1 = z1 / (1.f + expf(-z1));
    oo[lane]      = __float2half_rn(o0 * r * g0);
    oo[lane + 32] = __float2half_rn(o1 * r * g1);
}

// ---------------- launch ----------------
extern "C" void kernel_launch(void* const* d_in, const int* in_sizes, int n_in,
                              void* d_out, int out_size) {
    const float* x       = (const float*)d_in[0];
    const float* W_qkv   = (const float*)d_in[1];
    const float* conv_w  = (const float*)d_in[2];
    const float* W_z     = (const float*)d_in[3];
    const float* W_b     = (const float*)d_in[4];
    const float* W_a     = (const float*)d_in[5];
    const float* dt_bias = (const float*)d_in[6];
    const float* A_log   = (const float*)d_in[7];
    const float* W_out   = (const float*)d_in[8];
    float* out = (float*)d_out;

    void *p_mixed, *p_act, *p_z, *p_att, *p_eg, *p_o;
    void *p_xh, *p_wq, *p_wz, *p_wo, *p_oh;
    cudaGetSymbolAddress(&p_mixed, g_mixed);
    cudaGetSymbolAddress(&p_act,   g_act);
    cudaGetSymbolAddress(&p_z,     g_z);
    cudaGetSymbolAddress(&p_att,   g_att);
    cudaGetSymbolAddress(&p_eg,    g_eg);
    cudaGetSymbolAddress(&p_o,     g_o);
    cudaGetSymbolAddress(&p_xh,    g_xh);
    cudaGetSymbolAddress(&p_wq,    g_wqh);
    cudaGetSymbolAddress(&p_wz,    g_wzh);
    cudaGetSymbolAddress(&p_wo,    g_woh);
    cudaGetSymbolAddress(&p_oh,    g_oh);
    float* mixed = (float*)p_mixed;
    float* act   = (float*)p_act;
    float* zbuf  = (float*)p_z;
    float* att   = (float*)p_att;
    float* egb   = (float*)p_eg;
    float* obuf  = (float*)p_o;
    __half* xh  = (__half*)p_xh;
    __half* wqh = (__half*)p_wq;
    __half* wzh = (__half*)p_wz;
    __half* woh = (__half*)p_wo;
    __half* oh  = (__half*)p_oh;

    cudaFuncSetAttribute(hgemm_nt, cudaFuncAttributeMaxDynamicSharedMemorySize, GSMEM);

    // 0. fused fp16 pre-conversion (1 launch)
    cvt_all_kernel<<<(CVTOT + 255) / 256, 256>>>(
        (const float4*)x, (const float4*)W_qkv, (const float4*)W_z, (const float4*)W_out,
        (uint2*)xh, (uint2*)wqh, (uint2*)wzh, (uint2*)woh);

    // 1. qkv projection
    hgemm_nt<<<dim3(CONV / 128, MM / 128), 256, GSMEM>>>(xh, wqh, mixed, MM, CONV, DD);
    // 2. z projection
    hgemm_nt<<<dim3(DD / 128, MM / 128), 256, GSMEM>>>(xh, wzh, zbuf, MM, DD, DD);
    // 3. beta/g raw dots
    att_kernel<<<MM / 8, 256>>>(x, W_b, W_a, att);
    // 4. fused conv + silu + l2norm + beta/gate prep
    conv_prep_kernel<<<(MM * HH) / 4, 128>>>(mixed, conv_w, att, dt_bias, A_log, act, egb);
    // 5. sequential scan (staged, batched shuffles)
    scan_kernel<<<BB * HH * 8, 64>>>(act, egb, obuf);
    // 6. gated rmsnorm -> fp16
    post_kernel<<<(MM * HH) / 4, 128>>>(obuf, zbuf, oh);
    // 7. output projection -> d_out
    hgemm_nt<<<dim3(DD / 128, MM / 128), 256, GSMEM>>>(oh, woh, out, MM, DD, DD);
}

// round 14
// speedup vs baseline: 1.0274x; 1.0274x over previous
#include <cuda_runtime.h>
#include <cuda_fp16.h>
#include <cstdint>

// ---------------- problem constants ----------------
#define BB 2
#define TT 2048
#define DD 1024
#define HH 16
#define KK 4
#define HD 64
#define CONV (3*DD)
#define MM (BB*TT)          // 4096 tokens
#define CH 16               // staged scan chunk
#define NCH (TT / CH)

// ---------------- device scratch ----------------
__device__ float g_mixed[(size_t)MM * CONV];
__device__ float g_act[(size_t)MM * CONV];
__device__ float g_z[(size_t)MM * DD];
__device__ float g_att[(size_t)MM * 2 * HH];
__device__ float g_eg[(size_t)MM * HH];
__device__ float g_o[(size_t)MM * DD];
// fp16 pre-converted GEMM operands
__device__ __half g_xh[(size_t)MM * DD];
__device__ __half g_wqh[(size_t)CONV * DD];
__device__ __half g_wzh[(size_t)DD * DD];
__device__ __half g_woh[(size_t)DD * DD];
__device__ __half g_oh[(size_t)MM * DD];

__device__ __forceinline__ uint32_t smem_u32(const void* p) {
    uint32_t a;
    asm("{ .reg .u64 t; cvta.to.shared.u64 t, %1; cvt.u32.u64 %0, t; }" : "=r"(a) : "l"(p));
    return a;
}

#define LDSM_X4(r0, r1, r2, r3, addr)                                            \
    asm volatile("ldmatrix.sync.aligned.m8n8.x4.shared.b16 {%0,%1,%2,%3}, [%4];" \
                 : "=r"(r0), "=r"(r1), "=r"(r2), "=r"(r3) : "r"(addr))

// ---------------- fused fp16 cvt pre-pass (all 4 operands, 1 launch) ----------------
#define CV0 (MM * DD / 4)
#define CV1 (CONV * DD / 4)
#define CV2 (DD * DD / 4)
#define CVTOT (CV0 + CV1 + 2 * CV2)

__global__ __launch_bounds__(256) void cvt_all_kernel(const float4* __restrict__ x,
                                                      const float4* __restrict__ wq,
                                                      const float4* __restrict__ wz,
                                                      const float4* __restrict__ wo,
                                                      uint2* __restrict__ xh,
                                                      uint2* __restrict__ wqh,
                                                      uint2* __restrict__ wzh,
                                                      uint2* __restrict__ woh) {
    int i = blockIdx.x * 256 + threadIdx.x;
    const float4* src;
    uint2* dst;
    int off;
    if (i < CV0)                  { src = x;  dst = xh;  off = i; }
    else if (i < CV0 + CV1)       { src = wq; dst = wqh; off = i - CV0; }
    else if (i < CV0 + CV1 + CV2) { src = wz; dst = wzh; off = i - CV0 - CV1; }
    else                          { src = wo; dst = woh; off = i - CV0 - CV1 - CV2; }
    float4 v = src[off];
    __half2 lo = __floats2half2_rn(v.x, v.y);
    __half2 hi = __floats2half2_rn(v.z, v.w);
    dst[off] = make_uint2(*(uint32_t*)&lo, *(uint32_t*)&hi);
}

// ---------------- fp16 tensor-core GEMM: C[M,N] = A[M,K] @ W[N,K]^T ----------------
// 256 threads = 8 warps (2x4), block 128x128x32, warp tile 64x32.
// Fragment loads via ldmatrix.x4 (conflict-free on KPH=20 padded layout).
#define GBK 32
#define KPH 20
#define TILEW (128 * KPH)
#define BUFW (2 * TILEW)

__global__ __launch_bounds__(256) void hgemm_nt(const __half* __restrict__ A,
                                                const __half* __restrict__ W,
                                                float* __restrict__ C,
                                                int M, int N, int Kd) {
    __shared__ uint32_t sm[2 * BUFW];   // 40960 B
    int tid = threadIdx.x;
    int wid = tid >> 5;
    int lane = tid & 31;
    int bm = blockIdx.y * 128;
    int bn = blockIdx.x * 128;
    int wm = (wid & 1) * 64;
    int wn = (wid >> 1) * 32;
    int g = lane >> 2;
    int tg = lane & 3;

    uint32_t smbase = smem_u32(sm);
    int srow = tid >> 1;
    int shalf = tid & 1;
    const __half* Ap = A + (size_t)(bm + srow) * Kd + shalf * 16;
    const __half* Wp = W + (size_t)(bn + srow) * Kd + shalf * 16;
    uint32_t rowoff = srow * (KPH * 4) + shalf * 32;

    int lr = lane & 7;
    int lh = (lane >> 3) & 1;
    int lq = lane >> 4;
    uint32_t aBase[4];
#pragma unroll
    for (int mi = 0; mi < 4; mi++)
        aBase[mi] = smbase + (uint32_t)(wm + mi * 16 + lr + lh * 8) * (KPH * 4) + lq * 16;
    uint32_t bBase[2];
#pragma unroll
    for (int p = 0; p < 2; p++)
        bBase[p] = smbase + TILEW * 4 +
                   (uint32_t)(wn + p * 16 + lq * 8 + lr) * (KPH * 4) + lh * 16;

    float acc[4][4][4];
#pragma unroll
    for (int i = 0; i < 4; i++)
#pragma unroll
        for (int j = 0; j < 4; j++)
#pragma unroll
            for (int c = 0; c < 4; c++) acc[i][j][c] = 0.f;

#define STAGE(itx)                                                               \
    {                                                                            \
        uint32_t boff = smbase + ((itx) & 1) * (BUFW * 4) + rowoff;              \
        int ko = (itx) * GBK;                                                    \
        _Pragma("unroll")                                                        \
        for (int c = 0; c < 2; c++) {                                            \
            asm volatile("cp.async.cg.shared.global [%0], [%1], 16;"             \
                         :: "r"(boff + c * 16), "l"(Ap + ko + c * 8));           \
            asm volatile("cp.async.cg.shared.global [%0], [%1], 16;"             \
                         :: "r"(boff + TILEW * 4 + c * 16), "l"(Wp + ko + c * 8)); \
        }                                                                        \
        asm volatile("cp.async.commit_group;");                                  \
    }

    STAGE(0);

    int ntile = Kd / GBK;
    for (int it = 0; it < ntile; it++) {
        bool more = (it + 1) < ntile;
        if (more) STAGE(it + 1);
        if (more) asm volatile("cp.async.wait_group 1;");
        else      asm volatile("cp.async.wait_group 0;");
        __syncthreads();

        uint32_t bsel = (uint32_t)(it & 1) * (BUFW * 4);

#pragma unroll
        for (int ks = 0; ks < 2; ks++) {
            uint32_t kofs = bsel + ks * 32;
            uint32_t af[4][4];
            uint32_t bb[2][4];
#pragma unroll
            for (int mi = 0; mi < 4; mi++)
                LDSM_X4(af[mi][0], af[mi][1], af[mi][2], af[mi][3], aBase[mi] + kofs);
#pragma unroll
            for (int p = 0; p < 2; p++)
                LDSM_X4(bb[p][0], bb[p][1], bb[p][2], bb[p][3], bBase[p] + kofs);

#pragma unroll
            for (int mi = 0; mi < 4; mi++)
#pragma unroll
                for (int ni = 0; ni < 4; ni++) {
                    uint32_t b0 = bb[ni >> 1][(ni & 1) * 2];
                    uint32_t b1 = bb[ni >> 1][(ni & 1) * 2 + 1];
                    asm volatile(
                        "mma.sync.aligned.m16n8k16.row.col.f32.f16.f16.f32 "
                        "{%0,%1,%2,%3}, {%4,%5,%6,%7}, {%8,%9}, {%0,%1,%2,%3};"
                        : "+f"(acc[mi][ni][0]), "+f"(acc[mi][ni][1]),
                          "+f"(acc[mi][ni][2]), "+f"(acc[mi][ni][3])
                        : "r"(af[mi][0]), "r"(af[mi][1]), "r"(af[mi][2]), "r"(af[mi][3]),
                          "r"(b0), "r"(b1));
                }
        }
        __syncthreads();
    }
#undef STAGE

#pragma unroll
    for (int mi = 0; mi < 4; mi++) {
#pragma unroll
        for (int ni = 0; ni < 4; ni++) {
            int row0 = bm + wm + mi * 16 + g;
            int col = bn + wn + ni * 8 + tg * 2;
            *(float2*)(C + (size_t)row0 * N + col) =
                make_float2(acc[mi][ni][0], acc[mi][ni][1]);
            *(float2*)(C + (size_t)(row0 + 8) * N + col) =
                make_float2(acc[mi][ni][2], acc[mi][ni][3]);
        }
    }
}

// ---------------- beta/g raw projections, 16 tokens per block ----------------
#define ATT_SMEM (16 * DD * 4)
__global__ __launch_bounds__(256) void att_kernel(const float* __restrict__ x,
                                                  const float* __restrict__ Wb,
                                                  const float* __restrict__ Wa,
                                                  float* __restrict__ att) {
    extern __shared__ float xs[];   // [16][DD]
    int m0 = blockIdx.x * 16;
    int tid = threadIdx.x;
#pragma unroll
    for (int r = 0; r < 16; r++)
        *(float4*)&xs[r * DD + tid * 4] =
            *(const float4*)(x + (size_t)(m0 + r) * DD + tid * 4);
    __syncthreads();

    int g = tid >> 3;
    int sub = tid & 7;
    const float* w = (g < HH) ? (Wb + (size_t)g * DD) : (Wa + (size_t)(g - HH) * DD);
    float s[16];
#pragma unroll
    for (int r = 0; r < 16; r++) s[r] = 0.f;

    for (int j = sub * 4; j < DD; j += 32) {
        float4 wv = *(const float4*)(w + j);
#pragma unroll
        for (int r = 0; r < 16; r++) {
            float4 xv = *(const float4*)(&xs[r * DD + j]);
            s[r] += wv.x * xv.x + wv.y * xv.y + wv.z * xv.z + wv.w * xv.w;
        }
    }
#pragma unroll
    for (int r = 0; r < 16; r++) {
        s[r] += __shfl_xor_sync(0xffffffffu, s[r], 4);
        s[r] += __shfl_xor_sync(0xffffffffu, s[r], 2);
        s[r] += __shfl_xor_sync(0xffffffffu, s[r], 1);
        if (sub == 0) att[(size_t)(m0 + r) * 32 + g] = s[r];
    }
}

// ---------------- causal depthwise conv (K=4) + SiLU, strip-mined 8 t/thread ----------------
__global__ __launch_bounds__(256) void conv_silu_kernel(const float* __restrict__ mixed,
                                                        const float* __restrict__ cw,
                                                        float* __restrict__ out) {
    int idx = blockIdx.x * 256 + threadIdx.x;
    int c4 = idx % (CONV / 4);
    int mb = idx / (CONV / 4);
    int m0 = mb * 8;
    int t0 = m0 & (TT - 1);
    int c = c4 * 4;

    float4 w0 = *(const float4*)(cw + (size_t)(c + 0) * KK);
    float4 w1 = *(const float4*)(cw + (size_t)(c + 1) * KK);
    float4 w2 = *(const float4*)(cw + (size_t)(c + 2) * KK);
    float4 w3 = *(const float4*)(cw + (size_t)(c + 3) * KK);
    const float* wp0 = (const float*)&w0;
    const float* wp1 = (const float*)&w1;
    const float* wp2 = (const float*)&w2;
    const float* wp3 = (const float*)&w3;

    float4 win[4];
    const float4 zero4 = make_float4(0.f, 0.f, 0.f, 0.f);
#pragma unroll
    for (int s = 0; s < 3; s++) {
        win[s] = (t0 - 3 + s >= 0)
               ? *(const float4*)(mixed + (size_t)(m0 - 3 + s) * CONV + c)
               : zero4;
    }

#pragma unroll
    for (int tt = 0; tt < 8; tt++) {
        win[3] = *(const float4*)(mixed + (size_t)(m0 + tt) * CONV + c);
        float a0 = 0.f, a1 = 0.f, a2 = 0.f, a3 = 0.f;
#pragma unroll
        for (int j = 0; j < KK; j++) {
            a0 += wp0[j] * win[j].x;
            a1 += wp1[j] * win[j].y;
            a2 += wp2[j] * win[j].z;
            a3 += wp3[j] * win[j].w;
        }
        float4 r;
        r.x = a0 / (1.f + expf(-a0));
        r.y = a1 / (1.f + expf(-a1));
        r.z = a2 / (1.f + expf(-a2));
        r.w = a3 / (1.f + expf(-a3));
        *(float4*)(out + (size_t)(m0 + tt) * CONV + c) = r;
        win[0] = win[1]; win[1] = win[2]; win[2] = win[3];
    }
}

// ---------------- per-(m,h): l2norm q/k, v*=beta, eg=exp(g) ----------------
__global__ __launch_bounds__(128) void prep_kernel(float* __restrict__ act,
                                                   const float* __restrict__ att,
                                                   const float* __restrict__ dt_bias,
                                                   const float* __restrict__ A_log,
                                                   float* __restrict__ eg) {
    int w = blockIdx.x * 4 + (threadIdx.x >> 5);
    int lane = threadIdx.x & 31;
    int m = w >> 4;
    int h = w & (HH - 1);
    float* base = act + (size_t)m * CONV + h * HD;

    float q0 = base[lane], q1 = base[lane + 32];
    float sq = q0 * q0 + q1 * q1;
#pragma unroll
    for (int o = 16; o; o >>= 1) sq += __shfl_xor_sync(0xffffffffu, sq, o);
    float invq = rsqrtf(sq + 1e-6f) * 0.125f;
    base[lane] = q0 * invq;
    base[lane + 32] = q1 * invq;

    float k0 = base[DD + lane], k1 = base[DD + lane + 32];
    float sk = k0 * k0 + k1 * k1;
#pragma unroll
    for (int o = 16; o; o >>= 1) sk += __shfl_xor_sync(0xffffffffu, sk, o);
    float invk = rsqrtf(sk + 1e-6f);
    base[DD + lane] = k0 * invk;
    base[DD + lane + 32] = k1 * invk;

    float bdot = att[(size_t)m * 32 + h];
    float adot = att[(size_t)m * 32 + HH + h];
    float beta = 1.f / (1.f + expf(-bdot));
    float spin = adot + dt_bias[h];
    float sp = (spin > 20.f) ? spin : log1pf(expf(spin));
    float gg = -expf(A_log[h]) * sp;

    base[2 * DD + lane] *= beta;
    base[2 * DD + lane + 32] *= beta;
    if (lane == 0) eg[(size_t)m * HH + h] = expf(gg);
}

// ---------------- sequential gated scan, smem chunk-staged, batched shuffles ----------------
__global__ __launch_bounds__(64) void scan_kernel(const float* __restrict__ act,
                                                  const float* __restrict__ eg,
                                                  float* __restrict__ o) {
    __shared__ float sq[2][CH][64];
    __shared__ float sk[2][CH][64];
    __shared__ float sv[2][CH][8];
    __shared__ float se[2][CH];

    int bh = blockIdx.x >> 3;
    int cg = blockIdx.x & 7;
    int b = bh >> 4;
    int h = bh & (HH - 1);
    int tid = threadIdx.x;
    int vloc = tid >> 3;
    int part = tid & 7;
    int dbase = part * 8;
    int col = cg * 8 + vloc;

    float S[8];
#pragma unroll
    for (int i = 0; i < 8; i++) S[i] = 0.f;

    const float* abase = act + (size_t)b * TT * CONV + h * HD;
    const float* ebase = eg + (size_t)b * TT * HH + h;
    float* obase = o + (size_t)b * TT * DD + h * HD + col;

    int srow = tid >> 2;
    int sq4 = (tid & 3) * 16;
    uint32_t aq = smem_u32(&sq[0][0][0]);
    uint32_t ak = smem_u32(&sk[0][0][0]);
    uint32_t av = smem_u32(&sv[0][0][0]);
    uint32_t ae = smem_u32(&se[0][0]);

#define SSTAGE(cx)                                                                \
    {                                                                             \
        int bufx = (cx) & 1;                                                      \
        int t0 = (cx) * CH;                                                       \
        const float* gq = abase + (size_t)(t0 + srow) * CONV + sq4;               \
        const float* gk = gq + DD;                                                \
        uint32_t dq = aq + (bufx * CH * 64 + srow * 64 + sq4) * 4;                \
        uint32_t dk = ak + (bufx * CH * 64 + srow * 64 + sq4) * 4;                \
        _Pragma("unroll")                                                         \
        for (int j = 0; j < 4; j++) {                                             \
            asm volatile("cp.async.cg.shared.global [%0], [%1], 16;"              \
                         :: "r"(dq + j * 16), "l"(gq + j * 4));                   \
            asm volatile("cp.async.cg.shared.global [%0], [%1], 16;"              \
                         :: "r"(dk + j * 16), "l"(gk + j * 4));                   \
        }                                                                         \
        if (tid < 32) {                                                           \
            int tv = tid >> 1;                                                    \
            int c2 = (tid & 1) * 4;                                               \
            const float* gv = abase + (size_t)(t0 + tv) * CONV + 2 * DD           \
                              + cg * 8 + c2;                                      \
            uint32_t dv = av + (bufx * CH * 8 + tv * 8 + c2) * 4;                 \
            asm volatile("cp.async.ca.shared.global [%0], [%1], 16;"              \
                         :: "r"(dv), "l"(gv));                                    \
        }                                                                         \
        if (tid < 16) {                                                           \
            const float* ge = ebase + (size_t)(t0 + tid) * HH;                    \
            uint32_t de = ae + (bufx * CH + tid) * 4;                             \
            asm volatile("cp.async.ca.shared.global [%0], [%1], 4;"               \
                         :: "r"(de), "l"(ge));                                    \
        }                                                                         \
        asm volatile("cp.async.commit_group;");                                   \
    }

    SSTAGE(0);

    for (int c = 0; c < NCH; c++) {
        bool more = (c + 1) < NCH;
        if (more) SSTAGE(c + 1);
        if (more) asm volatile("cp.async.wait_group 1;");
        else      asm volatile("cp.async.wait_group 0;");
        __syncthreads();

        int buf = c & 1;
        float dots[CH];
#pragma unroll
        for (int tt = 0; tt < CH; tt++) {
            float qq[8], kk[8];
            *(float4*)(qq + 0) = *(const float4*)(&sq[buf][tt][dbase]);
            *(float4*)(qq + 4) = *(const float4*)(&sq[buf][tt][dbase + 4]);
            *(float4*)(kk + 0) = *(const float4*)(&sk[buf][tt][dbase]);
            *(float4*)(kk + 4) = *(const float4*)(&sk[buf][tt][dbase + 4]);
            float v = sv[buf][tt][vloc];
            float e = se[buf][tt];
            float dot = 0.f;
#pragma unroll
            for (int i = 0; i < 8; i++) {
                S[i] = S[i] * e + kk[i] * v;
                dot += qq[i] * S[i];
            }
            dots[tt] = dot;
        }
#pragma unroll
        for (int tt = 0; tt < CH; tt++) {
            float d = dots[tt];
            d += __shfl_xor_sync(0xffffffffu, d, 1);
            d += __shfl_xor_sync(0xffffffffu, d, 2);
            d += __shfl_xor_sync(0xffffffffu, d, 4);
            if (part == 0) obase[(size_t)(c * CH + tt) * DD] = d;
        }
        __syncthreads();
    }
#undef SSTAGE
}

// ---------------- gated RMSNorm over head dim -> fp16 for final projection ----------------
__global__ __launch_bounds__(128) void post_kernel(const float* __restrict__ o,
                                                   const float* __restrict__ z,
                                                   __half* __restrict__ oh) {
    int w = blockIdx.x * 4 + (threadIdx.x >> 5);
    int lane = threadIdx.x & 31;
    int m = w >> 4;
    int h = w & (HH - 1);
    const float* ob = o + (size_t)m * DD + h * HD;
    const float* zb = z + (size_t)m * DD + h * HD;
    __half* oo = oh + (size_t)m * DD + h * HD;

    float o0 = ob[lane], o1 = ob[lane + 32];
    float s = o0 * o0 + o1 * o1;
#pragma unroll
    for (int off = 16; off; off >>= 1) s += __shfl_xor_sync(0xffffffffu, s, off);
    float r = rsqrtf(s * (1.f / 64.f) + 1e-6f);

    float z0 = zb[lane], z1 = zb[lane + 32];
    float g0 = z0 / (1.f + expf(-z0));
    float g1 = z1 / (1.f + expf(-z1));
    oo[lane]      = __float2half_rn(o0 * r * g0);
    oo[lane + 32] = __float2half_rn(o1 * r * g1);
}

// ---------------- launch ----------------
extern "C" void kernel_launch(void* const* d_in, const int* in_sizes, int n_in,
                              void* d_out, int out_size) {
    const float* x       = (const float*)d_in[0];
    const float* W_qkv   = (const float*)d_in[1];
    const float* conv_w  = (const float*)d_in[2];
    const float* W_z     = (const float*)d_in[3];
    const float* W_b     = (const float*)d_in[4];
    const float* W_a     = (const float*)d_in[5];
    const float* dt_bias = (const float*)d_in[6];
    const float* A_log   = (const float*)d_in[7];
    const float* W_out   = (const float*)d_in[8];
    float* out = (float*)d_out;

    void *p_mixed, *p_act, *p_z, *p_att, *p_eg, *p_o;
    void *p_xh, *p_wq, *p_wz, *p_wo, *p_oh;
    cudaGetSymbolAddress(&p_mixed, g_mixed);
    cudaGetSymbolAddress(&p_act,   g_act);
    cudaGetSymbolAddress(&p_z,     g_z);
    cudaGetSymbolAddress(&p_att,   g_att);
    cudaGetSymbolAddress(&p_eg,    g_eg);
    cudaGetSymbolAddress(&p_o,     g_o);
    cudaGetSymbolAddress(&p_xh,    g_xh);
    cudaGetSymbolAddress(&p_wq,    g_wqh);
    cudaGetSymbolAddress(&p_wz,    g_wzh);
    cudaGetSymbolAddress(&p_wo,    g_woh);
    cudaGetSymbolAddress(&p_oh,    g_oh);
    float* mixed = (float*)p_mixed;
    float* act   = (float*)p_act;
    float* zbuf  = (float*)p_z;
    float* att   = (float*)p_att;
    float* egb   = (float*)p_eg;
    float* obuf  = (float*)p_o;
    __half* xh  = (__half*)p_xh;
    __half* wqh = (__half*)p_wq;
    __half* wzh = (__half*)p_wz;
    __half* woh = (__half*)p_wo;
    __half* oh  = (__half*)p_oh;

    cudaFuncSetAttribute(att_kernel, cudaFuncAttributeMaxDynamicSharedMemorySize, ATT_SMEM);

    // 0. fused fp16 pre-conversion (1 launch)
    cvt_all_kernel<<<(CVTOT + 255) / 256, 256>>>(
        (const float4*)x, (const float4*)W_qkv, (const float4*)W_z, (const float4*)W_out,
        (uint2*)xh, (uint2*)wqh, (uint2*)wzh, (uint2*)woh);

    // 1. qkv projection
    hgemm_nt<<<dim3(CONV / 128, MM / 128), 256>>>(xh, wqh, mixed, MM, CONV, DD);
    // 2. z projection
    hgemm_nt<<<dim3(DD / 128, MM / 128), 256>>>(xh, wzh, zbuf, MM, DD, DD);
    // 3. beta/g raw dots (16 tokens/block)
    att_kernel<<<MM / 16, 256, ATT_SMEM>>>(x, W_b, W_a, att);
    // 4. causal depthwise conv + silu
    conv_silu_kernel<<<((MM / 8) * (CONV / 4)) / 256, 256>>>(mixed, conv_w, act);
    // 5. l2norm q/k, v*beta, eg
    prep_kernel<<<(MM * HH) / 4, 128>>>(act, att, dt_bias, A_log, egb);
    // 6. sequential scan (staged, batched shuffles)
    scan_kernel<<<BB * HH * 8, 64>>>(act, egb, obuf);
    // 7. gated rmsnorm -> fp16
    post_kernel<<<(MM * HH) / 4, 128>>>(obuf, zbuf, oh);
    // 8. output projection -> d_out
    hgemm_nt<<<dim3(DD / 128, MM / 128), 256>>>(oh, woh, out, MM, DD, DD);
}

// round 15
// speedup vs baseline: 1.0397x; 1.0120x over previous
#include <cuda_runtime.h>
#include <cuda_fp16.h>
#include <cstdint>

// ---------------- problem constants ----------------
#define BB 2
#define TT 2048
#define DD 1024
#define HH 16
#define KK 4
#define HD 64
#define CONV (3*DD)
#define MM (BB*TT)          // 4096 tokens
#define CH 16               // staged scan chunk
#define NCH (TT / CH)

// ---------------- device scratch ----------------
__device__ __half g_mixedh[(size_t)MM * CONV];   // qkv pre-conv (fp16)
__device__ float g_act[(size_t)MM * CONV];
__device__ __half g_zh[(size_t)MM * DD];         // z (fp16)
__device__ float g_att[(size_t)MM * 2 * HH];
__device__ float g_eg[(size_t)MM * HH];
__device__ float g_o[(size_t)MM * DD];
// fp16 pre-converted GEMM operands
__device__ __half g_xh[(size_t)MM * DD];
__device__ __half g_wqh[(size_t)CONV * DD];
__device__ __half g_wzh[(size_t)DD * DD];
__device__ __half g_woh[(size_t)DD * DD];
__device__ __half g_oh[(size_t)MM * DD];

__device__ __forceinline__ uint32_t smem_u32(const void* p) {
    uint32_t a;
    asm("{ .reg .u64 t; cvta.to.shared.u64 t, %1; cvt.u32.u64 %0, t; }" : "=r"(a) : "l"(p));
    return a;
}

#define LDSM_X4(r0, r1, r2, r3, addr)                                            \
    asm volatile("ldmatrix.sync.aligned.m8n8.x4.shared.b16 {%0,%1,%2,%3}, [%4];" \
                 : "=r"(r0), "=r"(r1), "=r"(r2), "=r"(r3) : "r"(addr))

// ---------------- fused fp16 cvt pre-pass (all 4 operands, 1 launch) ----------------
#define CV0 (MM * DD / 4)
#define CV1 (CONV * DD / 4)
#define CV2 (DD * DD / 4)
#define CVTOT (CV0 + CV1 + 2 * CV2)

__global__ __launch_bounds__(256) void cvt_all_kernel(const float4* __restrict__ x,
                                                      const float4* __restrict__ wq,
                                                      const float4* __restrict__ wz,
                                                      const float4* __restrict__ wo,
                                                      uint2* __restrict__ xh,
                                                      uint2* __restrict__ wqh,
                                                      uint2* __restrict__ wzh,
                                                      uint2* __restrict__ woh) {
    int i = blockIdx.x * 256 + threadIdx.x;
    const float4* src;
    uint2* dst;
    int off;
    if (i < CV0)                  { src = x;  dst = xh;  off = i; }
    else if (i < CV0 + CV1)       { src = wq; dst = wqh; off = i - CV0; }
    else if (i < CV0 + CV1 + CV2) { src = wz; dst = wzh; off = i - CV0 - CV1; }
    else                          { src = wo; dst = woh; off = i - CV0 - CV1 - CV2; }
    float4 v = src[off];
    __half2 lo = __floats2half2_rn(v.x, v.y);
    __half2 hi = __floats2half2_rn(v.z, v.w);
    dst[off] = make_uint2(*(uint32_t*)&lo, *(uint32_t*)&hi);
}

// ---------------- fp16 tensor-core GEMM: C[M,N] = A[M,K] @ W[N,K]^T ----------------
// 256 threads = 8 warps (2x4), block 128x128x32, warp tile 64x32.
// half_out: 1 -> store C as fp16 (rn), 0 -> fp32.
#define GBK 32
#define KPH 20
#define TILEW (128 * KPH)
#define BUFW (2 * TILEW)

__global__ __launch_bounds__(256) void hgemm_nt(const __half* __restrict__ A,
                                                const __half* __restrict__ W,
                                                void* __restrict__ Cv,
                                                int M, int N, int Kd, int half_out) {
    __shared__ uint32_t sm[2 * BUFW];   // 40960 B
    int tid = threadIdx.x;
    int wid = tid >> 5;
    int lane = tid & 31;
    int bm = blockIdx.y * 128;
    int bn = blockIdx.x * 128;
    int wm = (wid & 1) * 64;
    int wn = (wid >> 1) * 32;
    int g = lane >> 2;
    int tg = lane & 3;

    uint32_t smbase = smem_u32(sm);
    int srow = tid >> 1;
    int shalf = tid & 1;
    const __half* Ap = A + (size_t)(bm + srow) * Kd + shalf * 16;
    const __half* Wp = W + (size_t)(bn + srow) * Kd + shalf * 16;
    uint32_t rowoff = srow * (KPH * 4) + shalf * 32;

    int lr = lane & 7;
    int lh = (lane >> 3) & 1;
    int lq = lane >> 4;
    uint32_t aBase[4];
#pragma unroll
    for (int mi = 0; mi < 4; mi++)
        aBase[mi] = smbase + (uint32_t)(wm + mi * 16 + lr + lh * 8) * (KPH * 4) + lq * 16;
    uint32_t bBase[2];
#pragma unroll
    for (int p = 0; p < 2; p++)
        bBase[p] = smbase + TILEW * 4 +
                   (uint32_t)(wn + p * 16 + lq * 8 + lr) * (KPH * 4) + lh * 16;

    float acc[4][4][4];
#pragma unroll
    for (int i = 0; i < 4; i++)
#pragma unroll
        for (int j = 0; j < 4; j++)
#pragma unroll
            for (int c = 0; c < 4; c++) acc[i][j][c] = 0.f;

#define STAGE(itx)                                                               \
    {                                                                            \
        uint32_t boff = smbase + ((itx) & 1) * (BUFW * 4) + rowoff;              \
        int ko = (itx) * GBK;                                                    \
        _Pragma("unroll")                                                        \
        for (int c = 0; c < 2; c++) {                                            \
            asm volatile("cp.async.cg.shared.global [%0], [%1], 16;"             \
                         :: "r"(boff + c * 16), "l"(Ap + ko + c * 8));           \
            asm volatile("cp.async.cg.shared.global [%0], [%1], 16;"             \
                         :: "r"(boff + TILEW * 4 + c * 16), "l"(Wp + ko + c * 8)); \
        }                                                                        \
        asm volatile("cp.async.commit_group;");                                  \
    }

    STAGE(0);

    int ntile = Kd / GBK;
    for (int it = 0; it < ntile; it++) {
        bool more = (it + 1) < ntile;
        if (more) STAGE(it + 1);
        if (more) asm volatile("cp.async.wait_group 1;");
        else      asm volatile("cp.async.wait_group 0;");
        __syncthreads();

        uint32_t bsel = (uint32_t)(it & 1) * (BUFW * 4);

#pragma unroll
        for (int ks = 0; ks < 2; ks++) {
            uint32_t kofs = bsel + ks * 32;
            uint32_t af[4][4];
            uint32_t bb[2][4];
#pragma unroll
            for (int mi = 0; mi < 4; mi++)
                LDSM_X4(af[mi][0], af[mi][1], af[mi][2], af[mi][3], aBase[mi] + kofs);
#pragma unroll
            for (int p = 0; p < 2; p++)
                LDSM_X4(bb[p][0], bb[p][1], bb[p][2], bb[p][3], bBase[p] + kofs);

#pragma unroll
            for (int mi = 0; mi < 4; mi++)
#pragma unroll
                for (int ni = 0; ni < 4; ni++) {
                    uint32_t b0 = bb[ni >> 1][(ni & 1) * 2];
                    uint32_t b1 = bb[ni >> 1][(ni & 1) * 2 + 1];
                    asm volatile(
                        "mma.sync.aligned.m16n8k16.row.col.f32.f16.f16.f32 "
                        "{%0,%1,%2,%3}, {%4,%5,%6,%7}, {%8,%9}, {%0,%1,%2,%3};"
                        : "+f"(acc[mi][ni][0]), "+f"(acc[mi][ni][1]),
                          "+f"(acc[mi][ni][2]), "+f"(acc[mi][ni][3])
                        : "r"(af[mi][0]), "r"(af[mi][1]), "r"(af[mi][2]), "r"(af[mi][3]),
                          "r"(b0), "r"(b1));
                }
        }
        __syncthreads();
    }
#undef STAGE

    if (half_out) {
        __half* Ch = (__half*)Cv;
#pragma unroll
        for (int mi = 0; mi < 4; mi++) {
#pragma unroll
            for (int ni = 0; ni < 4; ni++) {
                int row0 = bm + wm + mi * 16 + g;
                int col = bn + wn + ni * 8 + tg * 2;
                *(__half2*)(Ch + (size_t)row0 * N + col) =
                    __floats2half2_rn(acc[mi][ni][0], acc[mi][ni][1]);
                *(__half2*)(Ch + (size_t)(row0 + 8) * N + col) =
                    __floats2half2_rn(acc[mi][ni][2], acc[mi][ni][3]);
            }
        }
    } else {
        float* C = (float*)Cv;
#pragma unroll
        for (int mi = 0; mi < 4; mi++) {
#pragma unroll
            for (int ni = 0; ni < 4; ni++) {
                int row0 = bm + wm + mi * 16 + g;
                int col = bn + wn + ni * 8 + tg * 2;
                *(float2*)(C + (size_t)row0 * N + col) =
                    make_float2(acc[mi][ni][0], acc[mi][ni][1]);
                *(float2*)(C + (size_t)(row0 + 8) * N + col) =
                    make_float2(acc[mi][ni][2], acc[mi][ni][3]);
            }
        }
    }
}

// ---------------- beta/g raw projections, 8 tokens per block ----------------
__global__ __launch_bounds__(256) void att_kernel(const float* __restrict__ x,
                                                  const float* __restrict__ Wb,
                                                  const float* __restrict__ Wa,
                                                  float* __restrict__ att) {
    __shared__ float xs[8][DD];
    int m0 = blockIdx.x * 8;
    int tid = threadIdx.x;
#pragma unroll
    for (int r = 0; r < 8; r++)
        *(float4*)&xs[r][tid * 4] = *(const float4*)(x + (size_t)(m0 + r) * DD + tid * 4);
    __syncthreads();

    int g = tid >> 3;
    int sub = tid & 7;
    const float* w = (g < HH) ? (Wb + (size_t)g * DD) : (Wa + (size_t)(g - HH) * DD);
    float s[8];
#pragma unroll
    for (int r = 0; r < 8; r++) s[r] = 0.f;

    for (int j = sub * 4; j < DD; j += 32) {
        float4 wv = *(const float4*)(w + j);
#pragma unroll
        for (int r = 0; r < 8; r++) {
            float4 xv = *(const float4*)(&xs[r][j]);
            s[r] += wv.x * xv.x + wv.y * xv.y + wv.z * xv.z + wv.w * xv.w;
        }
    }
#pragma unroll
    for (int r = 0; r < 8; r++) {
        s[r] += __shfl_xor_sync(0xffffffffu, s[r], 4);
        s[r] += __shfl_xor_sync(0xffffffffu, s[r], 2);
        s[r] += __shfl_xor_sync(0xffffffffu, s[r], 1);
        if (sub == 0) att[(size_t)(m0 + r) * 32 + g] = s[r];
    }
}

// ---------------- causal depthwise conv (K=4) + SiLU; fp16 input, fp32 math ----------------
__global__ __launch_bounds__(256) void conv_silu_kernel(const __half* __restrict__ mixed,
                                                        const float* __restrict__ cw,
                                                        float* __restrict__ out) {
    int idx = blockIdx.x * 256 + threadIdx.x;
    int c4 = idx % (CONV / 4);
    int mb = idx / (CONV / 4);
    int m0 = mb * 8;
    int t0 = m0 & (TT - 1);
    int c = c4 * 4;

    float4 w0 = *(const float4*)(cw + (size_t)(c + 0) * KK);
    float4 w1 = *(const float4*)(cw + (size_t)(c + 1) * KK);
    float4 w2 = *(const float4*)(cw + (size_t)(c + 2) * KK);
    float4 w3 = *(const float4*)(cw + (size_t)(c + 3) * KK);
    const float* wp0 = (const float*)&w0;
    const float* wp1 = (const float*)&w1;
    const float* wp2 = (const float*)&w2;
    const float* wp3 = (const float*)&w3;

    float4 win[4];
    const float4 zero4 = make_float4(0.f, 0.f, 0.f, 0.f);
#pragma unroll
    for (int s = 0; s < 3; s++) {
        if (t0 - 3 + s >= 0) {
            uint2 hv = *(const uint2*)(mixed + (size_t)(m0 - 3 + s) * CONV + c);
            float2 f0 = __half22float2(*(__half2*)&hv.x);
            float2 f1 = __half22float2(*(__half2*)&hv.y);
            win[s] = make_float4(f0.x, f0.y, f1.x, f1.y);
        } else win[s] = zero4;
    }

#pragma unroll
    for (int tt = 0; tt < 8; tt++) {
        uint2 hv = *(const uint2*)(mixed + (size_t)(m0 + tt) * CONV + c);
        float2 f0 = __half22float2(*(__half2*)&hv.x);
        float2 f1 = __half22float2(*(__half2*)&hv.y);
        win[3] = make_float4(f0.x, f0.y, f1.x, f1.y);
        float a0 = 0.f, a1 = 0.f, a2 = 0.f, a3 = 0.f;
#pragma unroll
        for (int j = 0; j < KK; j++) {
            a0 += wp0[j] * win[j].x;
            a1 += wp1[j] * win[j].y;
            a2 += wp2[j] * win[j].z;
            a3 += wp3[j] * win[j].w;
        }
        float4 r;
        r.x = a0 / (1.f + expf(-a0));
        r.y = a1 / (1.f + expf(-a1));
        r.z = a2 / (1.f + expf(-a2));
        r.w = a3 / (1.f + expf(-a3));
        *(float4*)(out + (size_t)(m0 + tt) * CONV + c) = r;
        win[0] = win[1]; win[1] = win[2]; win[2] = win[3];
    }
}

// ---------------- per-(m,h): l2norm q/k, v*=beta, eg=exp(g) ----------------
__global__ __launch_bounds__(128) void prep_kernel(float* __restrict__ act,
                                                   const float* __restrict__ att,
                                                   const float* __restrict__ dt_bias,
                                                   const float* __restrict__ A_log,
                                                   float* __restrict__ eg) {
    int w = blockIdx.x * 4 + (threadIdx.x >> 5);
    int lane = threadIdx.x & 31;
    int m = w >> 4;
    int h = w & (HH - 1);
    float* base = act + (size_t)m * CONV + h * HD;

    float q0 = base[lane], q1 = base[lane + 32];
    float sq = q0 * q0 + q1 * q1;
#pragma unroll
    for (int o = 16; o; o >>= 1) sq += __shfl_xor_sync(0xffffffffu, sq, o);
    float invq = rsqrtf(sq + 1e-6f) * 0.125f;
    base[lane] = q0 * invq;
    base[lane + 32] = q1 * invq;

    float k0 = base[DD + lane], k1 = base[DD + lane + 32];
    float sk = k0 * k0 + k1 * k1;
#pragma unroll
    for (int o = 16; o; o >>= 1) sk += __shfl_xor_sync(0xffffffffu, sk, o);
    float invk = rsqrtf(sk + 1e-6f);
    base[DD + lane] = k0 * invk;
    base[DD + lane + 32] = k1 * invk;

    float bdot = att[(size_t)m * 32 + h];
    float adot = att[(size_t)m * 32 + HH + h];
    float beta = 1.f / (1.f + expf(-bdot));
    float spin = adot + dt_bias[h];
    float sp = (spin > 20.f) ? spin : log1pf(expf(spin));
    float gg = -expf(A_log[h]) * sp;

    base[2 * DD + lane] *= beta;
    base[2 * DD + lane + 32] *= beta;
    if (lane == 0) eg[(size_t)m * HH + h] = expf(gg);
}

// ---------------- sequential gated scan, smem chunk-staged, batched shuffles ----------------
__global__ __launch_bounds__(64) void scan_kernel(const float* __restrict__ act,
                                                  const float* __restrict__ eg,
                                                  float* __restrict__ o) {
    __shared__ float sq[2][CH][64];
    __shared__ float sk[2][CH][64];
    __shared__ float sv[2][CH][8];
    __shared__ float se[2][CH];

    int bh = blockIdx.x >> 3;
    int cg = blockIdx.x & 7;
    int b = bh >> 4;
    int h = bh & (HH - 1);
    int tid = threadIdx.x;
    int vloc = tid >> 3;
    int part = tid & 7;
    int dbase = part * 8;
    int col = cg * 8 + vloc;

    float S[8];
#pragma unroll
    for (int i = 0; i < 8; i++) S[i] = 0.f;

    const float* abase = act + (size_t)b * TT * CONV + h * HD;
    const float* ebase = eg + (size_t)b * TT * HH + h;
    float* obase = o + (size_t)b * TT * DD + h * HD + col;

    int srow = tid >> 2;
    int sq4 = (tid & 3) * 16;
    uint32_t aq = smem_u32(&sq[0][0][0]);
    uint32_t ak = smem_u32(&sk[0][0][0]);
    uint32_t av = smem_u32(&sv[0][0][0]);
    uint32_t ae = smem_u32(&se[0][0]);

#define SSTAGE(cx)                                                                \
    {                                                                             \
        int bufx = (cx) & 1;                                                      \
        int t0 = (cx) * CH;                                                       \
        const float* gq = abase + (size_t)(t0 + srow) * CONV + sq4;               \
        const float* gk = gq + DD;                                                \
        uint32_t dq = aq + (bufx * CH * 64 + srow * 64 + sq4) * 4;                \
        uint32_t dk = ak + (bufx * CH * 64 + srow * 64 + sq4) * 4;                \
        _Pragma("unroll")                                                         \
        for (int j = 0; j < 4; j++) {                                             \
            asm volatile("cp.async.cg.shared.global [%0], [%1], 16;"              \
                         :: "r"(dq + j * 16), "l"(gq + j * 4));                   \
            asm volatile("cp.async.cg.shared.global [%0], [%1], 16;"              \
                         :: "r"(dk + j * 16), "l"(gk + j * 4));                   \
        }                                                                         \
        if (tid < 32) {                                                           \
            int tv = tid >> 1;                                                    \
            int c2 = (tid & 1) * 4;                                               \
            const float* gv = abase + (size_t)(t0 + tv) * CONV + 2 * DD           \
                              + cg * 8 + c2;                                      \
            uint32_t dv = av + (bufx * CH * 8 + tv * 8 + c2) * 4;                 \
            asm volatile("cp.async.ca.shared.global [%0], [%1], 16;"              \
                         :: "r"(dv), "l"(gv));                                    \
        }                                                                         \
        if (tid < 16) {                                                           \
            const float* ge = ebase + (size_t)(t0 + tid) * HH;                    \
            uint32_t de = ae + (bufx * CH + tid) * 4;                             \
            asm volatile("cp.async.ca.shared.global [%0], [%1], 4;"               \
                         :: "r"(de), "l"(ge));                                    \
        }                                                                         \
        asm volatile("cp.async.commit_group;");                                   \
    }

    SSTAGE(0);

    for (int c = 0; c < NCH; c++) {
        bool more = (c + 1) < NCH;
        if (more) SSTAGE(c + 1);
        if (more) asm volatile("cp.async.wait_group 1;");
        else      asm volatile("cp.async.wait_group 0;");
        __syncthreads();

        int buf = c & 1;
        float dots[CH];
#pragma unroll
        for (int tt = 0; tt < CH; tt++) {
            float qq[8], kk[8];
            *(float4*)(qq + 0) = *(const float4*)(&sq[buf][tt][dbase]);
            *(float4*)(qq + 4) = *(const float4*)(&sq[buf][tt][dbase + 4]);
            *(float4*)(kk + 0) = *(const float4*)(&sk[buf][tt][dbase]);
            *(float4*)(kk + 4) = *(const float4*)(&sk[buf][tt][dbase + 4]);
            float v = sv[buf][tt][vloc];
            float e = se[buf][tt];
            float dot = 0.f;
#pragma unroll
            for (int i = 0; i < 8; i++) {
                S[i] = S[i] * e + kk[i] * v;
                dot += qq[i] * S[i];
            }
            dots[tt] = dot;
        }
#pragma unroll
        for (int tt = 0; tt < CH; tt++) {
            float d = dots[tt];
            d += __shfl_xor_sync(0xffffffffu, d, 1);
            d += __shfl_xor_sync(0xffffffffu, d, 2);
            d += __shfl_xor_sync(0xffffffffu, d, 4);
            if (part == 0) obase[(size_t)(c * CH + tt) * DD] = d;
        }
        __syncthreads();
    }
#undef SSTAGE
}

// ---------------- gated RMSNorm over head dim -> fp16 (z read as fp16) ----------------
__global__ __launch_bounds__(128) void post_kernel(const float* __restrict__ o,
                                                   const __half* __restrict__ z,
                                                   __half* __restrict__ oh) {
    int w = blockIdx.x * 4 + (threadIdx.x >> 5);
    int lane = threadIdx.x & 31;
    int m = w >> 4;
    int h = w & (HH - 1);
    const float* ob = o + (size_t)m * DD + h * HD;
    const __half* zb = z + (size_t)m * DD + h * HD;
    __half* oo = oh + (size_t)m * DD + h * HD;

    float o0 = ob[lane], o1 = ob[lane + 32];
    float s = o0 * o0 + o1 * o1;
#pragma unroll
    for (int off = 16; off; off >>= 1) s += __shfl_xor_sync(0xffffffffu, s, off);
    float r = rsqrtf(s * (1.f / 64.f) + 1e-6f);

    float z0 = __half2float(zb[lane]);
    float z1 = __half2float(zb[lane + 32]);
    float g0 = z0 / (1.f + expf(-z0));
    float g1 = z1 / (1.f + expf(-z1));
    oo[lane]      = __float2half_rn(o0 * r * g0);
    oo[lane + 32] = __float2half_rn(o1 * r * g1);
}

// ---------------- launch ----------------
extern "C" void kernel_launch(void* const* d_in, const int* in_sizes, int n_in,
                              void* d_out, int out_size) {
    const float* x       = (const float*)d_in[0];
    const float* W_qkv   = (const float*)d_in[1];
    const float* conv_w  = (const float*)d_in[2];
    const float* W_z     = (const float*)d_in[3];
    const float* W_b     = (const float*)d_in[4];
    const float* W_a     = (const float*)d_in[5];
    const float* dt_bias = (const float*)d_in[6];
    const float* A_log   = (const float*)d_in[7];
    const float* W_out   = (const float*)d_in[8];
    float* out = (float*)d_out;

    void *p_mixedh, *p_act, *p_zh, *p_att, *p_eg, *p_o;
    void *p_xh, *p_wq, *p_wz, *p_wo, *p_oh;
    cudaGetSymbolAddress(&p_mixedh, g_mixedh);
    cudaGetSymbolAddress(&p_act,   g_act);
    cudaGetSymbolAddress(&p_zh,    g_zh);
    cudaGetSymbolAddress(&p_att,   g_att);
    cudaGetSymbolAddress(&p_eg,    g_eg);
    cudaGetSymbolAddress(&p_o,     g_o);
    cudaGetSymbolAddress(&p_xh,    g_xh);
    cudaGetSymbolAddress(&p_wq,    g_wqh);
    cudaGetSymbolAddress(&p_wz,    g_wzh);
    cudaGetSymbolAddress(&p_wo,    g_woh);
    cudaGetSymbolAddress(&p_oh,    g_oh);
    __half* mixedh = (__half*)p_mixedh;
    float* act   = (float*)p_act;
    __half* zh   = (__half*)p_zh;
    float* att   = (float*)p_att;
    float* egb   = (float*)p_eg;
    float* obuf  = (float*)p_o;
    __half* xh  = (__half*)p_xh;
    __half* wqh = (__half*)p_wq;
    __half* wzh = (__half*)p_wz;
    __half* woh = (__half*)p_wo;
    __half* oh  = (__half*)p_oh;

    // 1. fused fp16 pre-conversion
    cvt_all_kernel<<<(CVTOT + 255) / 256, 256>>>(
        (const float4*)x, (const float4*)W_qkv, (const float4*)W_z, (const float4*)W_out,
        (uint2*)xh, (uint2*)wqh, (uint2*)wzh, (uint2*)woh);
    // 2. beta/g raw dots (moved early; depends only on x)
    att_kernel<<<MM / 8, 256>>>(x, W_b, W_a, att);
    // 3. qkv projection -> fp16 mixed
    hgemm_nt<<<dim3(CONV / 128, MM / 128), 256>>>(xh, wqh, mixedh, MM, CONV, DD, 1);
    // 4. z projection -> fp16 z   [PROFILED SLOT]
    hgemm_nt<<<dim3(DD / 128, MM / 128), 256>>>(xh, wzh, zh, MM, DD, DD, 1);
    // 5. causal depthwise conv + silu (fp16 in, fp32 out)
    conv_silu_kernel<<<((MM / 8) * (CONV / 4)) / 256, 256>>>(mixedh, conv_w, act);
    // 6. l2norm q/k, v*beta, eg
    prep_kernel<<<(MM * HH) / 4, 128>>>(act, att, dt_bias, A_log, egb);
    // 7. sequential scan
    scan_kernel<<<BB * HH * 8, 64>>>(act, egb, obuf);
    // 8. gated rmsnorm -> fp16
    post_kernel<<<(MM * HH) / 4, 128>>>(obuf, zh, oh);
    // 9. output projection -> d_out (fp32)
    hgemm_nt<<<dim3(DD / 128, MM / 128), 256>>>(oh, woh, out, MM, DD, DD, 0);
}

// round 16
// speedup vs baseline: 1.0522x; 1.0120x over previous
#include <cuda_runtime.h>
#include <cuda_fp16.h>
#include <cstdint>

// ---------------- problem constants ----------------
#define BB 2
#define TT 2048
#define DD 1024
#define HH 16
#define KK 4
#define HD 64
#define CONV (3*DD)
#define MM (BB*TT)          // 4096 tokens
#define CH 16               // staged scan chunk
#define NCH (TT / CH)

// ---------------- device scratch ----------------
__device__ __half g_mixedh[(size_t)MM * CONV];   // qkv pre-conv (fp16)
__device__ float g_act[(size_t)MM * CONV];
__device__ __half g_zh[(size_t)MM * DD];         // z (fp16)
__device__ float g_att[(size_t)MM * 2 * HH];
__device__ float g_eg[(size_t)MM * HH];
__device__ float g_o[(size_t)MM * DD];
// fp16 pre-converted GEMM operands
__device__ __half g_xh[(size_t)MM * DD];
__device__ __half g_wqh[(size_t)CONV * DD];
__device__ __half g_wzh[(size_t)DD * DD];
__device__ __half g_woh[(size_t)DD * DD];
__device__ __half g_oh[(size_t)MM * DD];

__device__ __forceinline__ uint32_t smem_u32(const void* p) {
    uint32_t a;
    asm("{ .reg .u64 t; cvta.to.shared.u64 t, %1; cvt.u32.u64 %0, t; }" : "=r"(a) : "l"(p));
    return a;
}

#define LDSM_X4(r0, r1, r2, r3, addr)                                            \
    asm volatile("ldmatrix.sync.aligned.m8n8.x4.shared.b16 {%0,%1,%2,%3}, [%4];" \
                 : "=r"(r0), "=r"(r1), "=r"(r2), "=r"(r3) : "r"(addr))

// ---------------- fused fp16 cvt pre-pass (all 4 operands, 1 launch) ----------------
#define CV0 (MM * DD / 4)
#define CV1 (CONV * DD / 4)
#define CV2 (DD * DD / 4)
#define CVTOT (CV0 + CV1 + 2 * CV2)

__global__ __launch_bounds__(256) void cvt_all_kernel(const float4* __restrict__ x,
                                                      const float4* __restrict__ wq,
                                                      const float4* __restrict__ wz,
                                                      const float4* __restrict__ wo,
                                                      uint2* __restrict__ xh,
                                                      uint2* __restrict__ wqh,
                                                      uint2* __restrict__ wzh,
                                                      uint2* __restrict__ woh) {
    int i = blockIdx.x * 256 + threadIdx.x;
    const float4* src;
    uint2* dst;
    int off;
    if (i < CV0)                  { src = x;  dst = xh;  off = i; }
    else if (i < CV0 + CV1)       { src = wq; dst = wqh; off = i - CV0; }
    else if (i < CV0 + CV1 + CV2) { src = wz; dst = wzh; off = i - CV0 - CV1; }
    else                          { src = wo; dst = woh; off = i - CV0 - CV1 - CV2; }
    float4 v = src[off];
    __half2 lo = __floats2half2_rn(v.x, v.y);
    __half2 hi = __floats2half2_rn(v.z, v.w);
    dst[off] = make_uint2(*(uint32_t*)&lo, *(uint32_t*)&hi);
}

// ---------------- fp16 tensor-core GEMM: C[M,N] = A[M,K] @ W[N,K]^T ----------------
// 256 threads = 8 warps (2x4), block 128x128x32, warp tile 64x32.
// 3-stage cp.async pipeline (wait_group 2 steady-state) to cover staging latency.
#define GBK 32
#define KPH 20
#define TILEW (128 * KPH)
#define BUFW (2 * TILEW)
#define NSTG 3
#define GSMEM3 (NSTG * BUFW * 4)     // 61440 bytes (dynamic)

__global__ __launch_bounds__(256) void hgemm_nt(const __half* __restrict__ A,
                                                const __half* __restrict__ W,
                                                void* __restrict__ Cv,
                                                int M, int N, int Kd, int half_out) {
    extern __shared__ uint32_t sm[];
    int tid = threadIdx.x;
    int wid = tid >> 5;
    int lane = tid & 31;
    int bm = blockIdx.y * 128;
    int bn = blockIdx.x * 128;
    int wm = (wid & 1) * 64;
    int wn = (wid >> 1) * 32;
    int g = lane >> 2;
    int tg = lane & 3;

    uint32_t smbase = smem_u32(sm);
    int srow = tid >> 1;
    int shalf = tid & 1;
    const __half* Ap = A + (size_t)(bm + srow) * Kd + shalf * 16;
    const __half* Wp = W + (size_t)(bn + srow) * Kd + shalf * 16;
    uint32_t rowoff = srow * (KPH * 4) + shalf * 32;

    int lr = lane & 7;
    int lh = (lane >> 3) & 1;
    int lq = lane >> 4;
    uint32_t aBase[4];
#pragma unroll
    for (int mi = 0; mi < 4; mi++)
        aBase[mi] = smbase + (uint32_t)(wm + mi * 16 + lr + lh * 8) * (KPH * 4) + lq * 16;
    uint32_t bBase[2];
#pragma unroll
    for (int p = 0; p < 2; p++)
        bBase[p] = smbase + TILEW * 4 +
                   (uint32_t)(wn + p * 16 + lq * 8 + lr) * (KPH * 4) + lh * 16;

    float acc[4][4][4];
#pragma unroll
    for (int i = 0; i < 4; i++)
#pragma unroll
        for (int j = 0; j < 4; j++)
#pragma unroll
            for (int c = 0; c < 4; c++) acc[i][j][c] = 0.f;

#define STAGE(itx)                                                               \
    {                                                                            \
        uint32_t boff = smbase + (uint32_t)((itx) % NSTG) * (BUFW * 4) + rowoff; \
        int ko = (itx) * GBK;                                                    \
        _Pragma("unroll")                                                        \
        for (int c = 0; c < 2; c++) {                                            \
            asm volatile("cp.async.cg.shared.global [%0], [%1], 16;"             \
                         :: "r"(boff + c * 16), "l"(Ap + ko + c * 8));           \
            asm volatile("cp.async.cg.shared.global [%0], [%1], 16;"             \
                         :: "r"(boff + TILEW * 4 + c * 16), "l"(Wp + ko + c * 8)); \
        }                                                                        \
        asm volatile("cp.async.commit_group;");                                  \
    }

    STAGE(0);
    STAGE(1);

    int ntile = Kd / GBK;
    for (int it = 0; it < ntile; it++) {
        if (it + 2 < ntile) {
            STAGE(it + 2);
            asm volatile("cp.async.wait_group 2;");
        } else if (it + 1 < ntile) {
            asm volatile("cp.async.wait_group 1;");
        } else {
            asm volatile("cp.async.wait_group 0;");
        }
        __syncthreads();

        uint32_t bsel = (uint32_t)(it % NSTG) * (BUFW * 4);

#pragma unroll
        for (int ks = 0; ks < 2; ks++) {
            uint32_t kofs = bsel + ks * 32;
            uint32_t af[4][4];
            uint32_t bb[2][4];
#pragma unroll
            for (int mi = 0; mi < 4; mi++)
                LDSM_X4(af[mi][0], af[mi][1], af[mi][2], af[mi][3], aBase[mi] + kofs);
#pragma unroll
            for (int p = 0; p < 2; p++)
                LDSM_X4(bb[p][0], bb[p][1], bb[p][2], bb[p][3], bBase[p] + kofs);

#pragma unroll
            for (int mi = 0; mi < 4; mi++)
#pragma unroll
                for (int ni = 0; ni < 4; ni++) {
                    uint32_t b0 = bb[ni >> 1][(ni & 1) * 2];
                    uint32_t b1 = bb[ni >> 1][(ni & 1) * 2 + 1];
                    asm volatile(
                        "mma.sync.aligned.m16n8k16.row.col.f32.f16.f16.f32 "
                        "{%0,%1,%2,%3}, {%4,%5,%6,%7}, {%8,%9}, {%0,%1,%2,%3};"
                        : "+f"(acc[mi][ni][0]), "+f"(acc[mi][ni][1]),
                          "+f"(acc[mi][ni][2]), "+f"(acc[mi][ni][3])
                        : "r"(af[mi][0]), "r"(af[mi][1]), "r"(af[mi][2]), "r"(af[mi][3]),
                          "r"(b0), "r"(b1));
                }
        }
        __syncthreads();
    }
#undef STAGE

    if (half_out) {
        __half* Ch = (__half*)Cv;
#pragma unroll
        for (int mi = 0; mi < 4; mi++) {
#pragma unroll
            for (int ni = 0; ni < 4; ni++) {
                int row0 = bm + wm + mi * 16 + g;
                int col = bn + wn + ni * 8 + tg * 2;
                *(__half2*)(Ch + (size_t)row0 * N + col) =
                    __floats2half2_rn(acc[mi][ni][0], acc[mi][ni][1]);
                *(__half2*)(Ch + (size_t)(row0 + 8) * N + col) =
                    __floats2half2_rn(acc[mi][ni][2], acc[mi][ni][3]);
            }
        }
    } else {
        float* C = (float*)Cv;
#pragma unroll
        for (int mi = 0; mi < 4; mi++) {
#pragma unroll
            for (int ni = 0; ni < 4; ni++) {
                int row0 = bm + wm + mi * 16 + g;
                int col = bn + wn + ni * 8 + tg * 2;
                *(float2*)(C + (size_t)row0 * N + col) =
                    make_float2(acc[mi][ni][0], acc[mi][ni][1]);
                *(float2*)(C + (size_t)(row0 + 8) * N + col) =
                    make_float2(acc[mi][ni][2], acc[mi][ni][3]);
            }
        }
    }
}

// ---------------- beta/g raw projections, 8 tokens per block ----------------
__global__ __launch_bounds__(256) void att_kernel(const float* __restrict__ x,
                                                  const float* __restrict__ Wb,
                                                  const float* __restrict__ Wa,
                                                  float* __restrict__ att) {
    __shared__ float xs[8][DD];
    int m0 = blockIdx.x * 8;
    int tid = threadIdx.x;
#pragma unroll
    for (int r = 0; r < 8; r++)
        *(float4*)&xs[r][tid * 4] = *(const float4*)(x + (size_t)(m0 + r) * DD + tid * 4);
    __syncthreads();

    int g = tid >> 3;
    int sub = tid & 7;
    const float* w = (g < HH) ? (Wb + (size_t)g * DD) : (Wa + (size_t)(g - HH) * DD);
    float s[8];
#pragma unroll
    for (int r = 0; r < 8; r++) s[r] = 0.f;

    for (int j = sub * 4; j < DD; j += 32) {
        float4 wv = *(const float4*)(w + j);
#pragma unroll
        for (int r = 0; r < 8; r++) {
            float4 xv = *(const float4*)(&xs[r][j]);
            s[r] += wv.x * xv.x + wv.y * xv.y + wv.z * xv.z + wv.w * xv.w;
        }
    }
#pragma unroll
    for (int r = 0; r < 8; r++) {
        s[r] += __shfl_xor_sync(0xffffffffu, s[r], 4);
        s[r] += __shfl_xor_sync(0xffffffffu, s[r], 2);
        s[r] += __shfl_xor_sync(0xffffffffu, s[r], 1);
        if (sub == 0) att[(size_t)(m0 + r) * 32 + g] = s[r];
    }
}

// ---------------- causal depthwise conv (K=4) + SiLU; fp16 input, fp32 math ----------------
__global__ __launch_bounds__(256) void conv_silu_kernel(const __half* __restrict__ mixed,
                                                        const float* __restrict__ cw,
                                                        float* __restrict__ out) {
    int idx = blockIdx.x * 256 + threadIdx.x;
    int c4 = idx % (CONV / 4);
    int mb = idx / (CONV / 4);
    int m0 = mb * 8;
    int t0 = m0 & (TT - 1);
    int c = c4 * 4;

    float4 w0 = *(const float4*)(cw + (size_t)(c + 0) * KK);
    float4 w1 = *(const float4*)(cw + (size_t)(c + 1) * KK);
    float4 w2 = *(const float4*)(cw + (size_t)(c + 2) * KK);
    float4 w3 = *(const float4*)(cw + (size_t)(c + 3) * KK);
    const float* wp0 = (const float*)&w0;
    const float* wp1 = (const float*)&w1;
    const float* wp2 = (const float*)&w2;
    const float* wp3 = (const float*)&w3;

    float4 win[4];
    const float4 zero4 = make_float4(0.f, 0.f, 0.f, 0.f);
#pragma unroll
    for (int s = 0; s < 3; s++) {
        if (t0 - 3 + s >= 0) {
            uint2 hv = *(const uint2*)(mixed + (size_t)(m0 - 3 + s) * CONV + c);
            float2 f0 = __half22float2(*(__half2*)&hv.x);
            float2 f1 = __half22float2(*(__half2*)&hv.y);
            win[s] = make_float4(f0.x, f0.y, f1.x, f1.y);
        } else win[s] = zero4;
    }

#pragma unroll
    for (int tt = 0; tt < 8; tt++) {
        uint2 hv = *(const uint2*)(mixed + (size_t)(m0 + tt) * CONV + c);
        float2 f0 = __half22float2(*(__half2*)&hv.x);
        float2 f1 = __half22float2(*(__half2*)&hv.y);
        win[3] = make_float4(f0.x, f0.y, f1.x, f1.y);
        float a0 = 0.f, a1 = 0.f, a2 = 0.f, a3 = 0.f;
#pragma unroll
        for (int j = 0; j < KK; j++) {
            a0 += wp0[j] * win[j].x;
            a1 += wp1[j] * win[j].y;
            a2 += wp2[j] * win[j].z;
            a3 += wp3[j] * win[j].w;
        }
        float4 r;
        r.x = a0 / (1.f + expf(-a0));
        r.y = a1 / (1.f + expf(-a1));
        r.z = a2 / (1.f + expf(-a2));
        r.w = a3 / (1.f + expf(-a3));
        *(float4*)(out + (size_t)(m0 + tt) * CONV + c) = r;
        win[0] = win[1]; win[1] = win[2]; win[2] = win[3];
    }
}

// ---------------- per-(m,h): l2norm q/k, v*=beta, eg=exp(g) ----------------
__global__ __launch_bounds__(128) void prep_kernel(float* __restrict__ act,
                                                   const float* __restrict__ att,
                                                   const float* __restrict__ dt_bias,
                                                   const float* __restrict__ A_log,
                                                   float* __restrict__ eg) {
    int w = blockIdx.x * 4 + (threadIdx.x >> 5);
    int lane = threadIdx.x & 31;
    int m = w >> 4;
    int h = w & (HH - 1);
    float* base = act + (size_t)m * CONV + h * HD;

    float q0 = base[lane], q1 = base[lane + 32];
    float sq = q0 * q0 + q1 * q1;
#pragma unroll
    for (int o = 16; o; o >>= 1) sq += __shfl_xor_sync(0xffffffffu, sq, o);
    float invq = rsqrtf(sq + 1e-6f) * 0.125f;
    base[lane] = q0 * invq;
    base[lane + 32] = q1 * invq;

    float k0 = base[DD + lane], k1 = base[DD + lane + 32];
    float sk = k0 * k0 + k1 * k1;
#pragma unroll
    for (int o = 16; o; o >>= 1) sk += __shfl_xor_sync(0xffffffffu, sk, o);
    float invk = rsqrtf(sk + 1e-6f);
    base[DD + lane] = k0 * invk;
    base[DD + lane + 32] = k1 * invk;

    float bdot = att[(size_t)m * 32 + h];
    float adot = att[(size_t)m * 32 + HH + h];
    float beta = 1.f / (1.f + expf(-bdot));
    float spin = adot + dt_bias[h];
    float sp = (spin > 20.f) ? spin : log1pf(expf(spin));
    float gg = -expf(A_log[h]) * sp;

    base[2 * DD + lane] *= beta;
    base[2 * DD + lane + 32] *= beta;
    if (lane == 0) eg[(size_t)m * HH + h] = expf(gg);
}

// ---------------- sequential gated scan, smem chunk-staged, batched shuffles ----------------
__global__ __launch_bounds__(64) void scan_kernel(const float* __restrict__ act,
                                                  const float* __restrict__ eg,
                                                  float* __restrict__ o) {
    __shared__ float sq[2][CH][64];
    __shared__ float sk[2][CH][64];
    __shared__ float sv[2][CH][8];
    __shared__ float se[2][CH];

    int bh = blockIdx.x >> 3;
    int cg = blockIdx.x & 7;
    int b = bh >> 4;
    int h = bh & (HH - 1);
    int tid = threadIdx.x;
    int vloc = tid >> 3;
    int part = tid & 7;
    int dbase = part * 8;
    int col = cg * 8 + vloc;

    float S[8];
#pragma unroll
    for (int i = 0; i < 8; i++) S[i] = 0.f;

    const float* abase = act + (size_t)b * TT * CONV + h * HD;
    const float* ebase = eg + (size_t)b * TT * HH + h;
    float* obase = o + (size_t)b * TT * DD + h * HD + col;

    int srow = tid >> 2;
    int sq4 = (tid & 3) * 16;
    uint32_t aq = smem_u32(&sq[0][0][0]);
    uint32_t ak = smem_u32(&sk[0][0][0]);
    uint32_t av = smem_u32(&sv[0][0][0]);
    uint32_t ae = smem_u32(&se[0][0]);

#define SSTAGE(cx)                                                                \
    {                                                                             \
        int bufx = (cx) & 1;                                                      \
        int t0 = (cx) * CH;                                                       \
        const float* gq = abase + (size_t)(t0 + srow) * CONV + sq4;               \
        const float* gk = gq + DD;                                                \
        uint32_t dq = aq + (bufx * CH * 64 + srow * 64 + sq4) * 4;                \
        uint32_t dk = ak + (bufx * CH * 64 + srow * 64 + sq4) * 4;                \
        _Pragma("unroll")                                                         \
        for (int j = 0; j < 4; j++) {                                             \
            asm volatile("cp.async.cg.shared.global [%0], [%1], 16;"              \
                         :: "r"(dq + j * 16), "l"(gq + j * 4));                   \
            asm volatile("cp.async.cg.shared.global [%0], [%1], 16;"              \
                         :: "r"(dk + j * 16), "l"(gk + j * 4));                   \
        }                                                                         \
        if (tid < 32) {                                                           \
            int tv = tid >> 1;                                                    \
            int c2 = (tid & 1) * 4;                                               \
            const float* gv = abase + (size_t)(t0 + tv) * CONV + 2 * DD           \
                              + cg * 8 + c2;                                      \
            uint32_t dv = av + (bufx * CH * 8 + tv * 8 + c2) * 4;                 \
            asm volatile("cp.async.ca.shared.global [%0], [%1], 16;"              \
                         :: "r"(dv), "l"(gv));                                    \
        }                                                                         \
        if (tid < 16) {                                                           \
            const float* ge = ebase + (size_t)(t0 + tid) * HH;                    \
            uint32_t de = ae + (bufx * CH + tid) * 4;                             \
            asm volatile("cp.async.ca.shared.global [%0], [%1], 4;"               \
                         :: "r"(de), "l"(ge));                                    \
        }                                                                         \
        asm volatile("cp.async.commit_group;");                                   \
    }

    SSTAGE(0);

    for (int c = 0; c < NCH; c++) {
        bool more = (c + 1) < NCH;
        if (more) SSTAGE(c + 1);
        if (more) asm volatile("cp.async.wait_group 1;");
        else      asm volatile("cp.async.wait_group 0;");
        __syncthreads();

        int buf = c & 1;
        float dots[CH];
#pragma unroll
        for (int tt = 0; tt < CH; tt++) {
            float qq[8], kk[8];
            *(float4*)(qq + 0) = *(const float4*)(&sq[buf][tt][dbase]);
            *(float4*)(qq + 4) = *(const float4*)(&sq[buf][tt][dbase + 4]);
            *(float4*)(kk + 0) = *(const float4*)(&sk[buf][tt][dbase]);
            *(float4*)(kk + 4) = *(const float4*)(&sk[buf][tt][dbase + 4]);
            float v = sv[buf][tt][vloc];
            float e = se[buf][tt];
            float dot = 0.f;
#pragma unroll
            for (int i = 0; i < 8; i++) {
                S[i] = S[i] * e + kk[i] * v;
                dot += qq[i] * S[i];
            }
            dots[tt] = dot;
        }
#pragma unroll
        for (int tt = 0; tt < CH; tt++) {
            float d = dots[tt];
            d += __shfl_xor_sync(0xffffffffu, d, 1);
            d += __shfl_xor_sync(0xffffffffu, d, 2);
            d += __shfl_xor_sync(0xffffffffu, d, 4);
            if (part == 0) obase[(size_t)(c * CH + tt) * DD] = d;
        }
        __syncthreads();
    }
#undef SSTAGE
}

// ---------------- gated RMSNorm over head dim -> fp16 (z read as fp16) ----------------
__global__ __launch_bounds__(128) void post_kernel(const float* __restrict__ o,
                                                   const __half* __restrict__ z,
                                                   __half* __restrict__ oh) {
    int w = blockIdx.x * 4 + (threadIdx.x >> 5);
    int lane = threadIdx.x & 31;
    int m = w >> 4;
    int h = w & (HH - 1);
    const float* ob = o + (size_t)m * DD + h * HD;
    const __half* zb = z + (size_t)m * DD + h * HD;
    __half* oo = oh + (size_t)m * DD + h * HD;

    float o0 = ob[lane], o1 = ob[lane + 32];
    float s = o0 * o0 + o1 * o1;
#pragma unroll
    for (int off = 16; off; off >>= 1) s += __shfl_xor_sync(0xffffffffu, s, off);
    float r = rsqrtf(s * (1.f / 64.f) + 1e-6f);

    float z0 = __half2float(zb[lane]);
    float z1 = __half2float(zb[lane + 32]);
    float g0 = z0 / (1.f + expf(-z0));
    float g1 = z1 / (1.f + expf(-z1));
    oo[lane]      = __float2half_rn(o0 * r * g0);
    oo[lane + 32] = __float2half_rn(o1 * r * g1);
}

// ---------------- launch ----------------
extern "C" void kernel_launch(void* const* d_in, const int* in_sizes, int n_in,
                              void* d_out, int out_size) {
    const float* x       = (const float*)d_in[0];
    const float* W_qkv   = (const float*)d_in[1];
    const float* conv_w  = (const float*)d_in[2];
    const float* W_z     = (const float*)d_in[3];
    const float* W_b     = (const float*)d_in[4];
    const float* W_a     = (const float*)d_in[5];
    const float* dt_bias = (const float*)d_in[6];
    const float* A_log   = (const float*)d_in[7];
    const float* W_out   = (const float*)d_in[8];
    float* out = (float*)d_out;

    void *p_mixedh, *p_act, *p_zh, *p_att, *p_eg, *p_o;
    void *p_xh, *p_wq, *p_wz, *p_wo, *p_oh;
    cudaGetSymbolAddress(&p_mixedh, g_mixedh);
    cudaGetSymbolAddress(&p_act,   g_act);
    cudaGetSymbolAddress(&p_zh,    g_zh);
    cudaGetSymbolAddress(&p_att,   g_att);
    cudaGetSymbolAddress(&p_eg,    g_eg);
    cudaGetSymbolAddress(&p_o,     g_o);
    cudaGetSymbolAddress(&p_xh,    g_xh);
    cudaGetSymbolAddress(&p_wq,    g_wqh);
    cudaGetSymbolAddress(&p_wz,    g_wzh);
    cudaGetSymbolAddress(&p_wo,    g_woh);
    cudaGetSymbolAddress(&p_oh,    g_oh);
    __half* mixedh = (__half*)p_mixedh;
    float* act   = (float*)p_act;
    __half* zh   = (__half*)p_zh;
    float* att   = (float*)p_att;
    float* egb   = (float*)p_eg;
    float* obuf  = (float*)p_o;
    __half* xh  = (__half*)p_xh;
    __half* wqh = (__half*)p_wq;
    __half* wzh = (__half*)p_wz;
    __half* woh = (__half*)p_wo;
    __half* oh  = (__half*)p_oh;

    cudaFuncSetAttribute(hgemm_nt, cudaFuncAttributeMaxDynamicSharedMemorySize, GSMEM3);

    // 1. fused fp16 pre-conversion
    cvt_all_kernel<<<(CVTOT + 255) / 256, 256>>>(
        (const float4*)x, (const float4*)W_qkv, (const float4*)W_z, (const float4*)W_out,
        (uint2*)xh, (uint2*)wqh, (uint2*)wzh, (uint2*)woh);
    // 2. beta/g raw dots
    att_kernel<<<MM / 8, 256>>>(x, W_b, W_a, att);
    // 3. qkv projection -> fp16 mixed
    hgemm_nt<<<dim3(CONV / 128, MM / 128), 256, GSMEM3>>>(xh, wqh, mixedh, MM, CONV, DD, 1);
    // 4. z projection -> fp16 z   [PROFILED SLOT]
    hgemm_nt<<<dim3(DD / 128, MM / 128), 256, GSMEM3>>>(xh, wzh, zh, MM, DD, DD, 1);
    // 5. causal depthwise conv + silu
    conv_silu_kernel<<<((MM / 8) * (CONV / 4)) / 256, 256>>>(mixedh, conv_w, act);
    // 6. l2norm q/k, v*beta, eg
    prep_kernel<<<(MM * HH) / 4, 128>>>(act, att, dt_bias, A_log, egb);
    // 7. sequential scan
    scan_kernel<<<BB * HH * 8, 64>>>(act, egb, obuf);
    // 8. gated rmsnorm -> fp16
    post_kernel<<<(MM * HH) / 4, 128>>>(obuf, zh, oh);
    // 9. output projection -> d_out (fp32)
    hgemm_nt<<<dim3(DD / 128, MM / 128), 256, GSMEM3>>>(oh, woh, out, MM, DD, DD, 0);
}

// round 17
// speedup vs baseline: 1.1048x; 1.0499x over previous
#include <cuda_runtime.h>
#include <cuda_fp16.h>
#include <cstdint>

// ---------------- problem constants ----------------
#define BB 2
#define TT 2048
#define DD 1024
#define HH 16
#define KK 4
#define HD 64
#define CONV (3*DD)
#define MM (BB*TT)          // 4096 tokens
#define CH 16               // staged scan chunk
#define NCH (TT / CH)

// ---------------- device scratch ----------------
__device__ __half g_mixedh[(size_t)MM * CONV];   // qkv pre-conv (fp16)
__device__ float g_act[(size_t)MM * CONV];
__device__ __half g_zh[(size_t)MM * DD];         // z (fp16)
__device__ float g_att[(size_t)MM * 2 * HH];
__device__ float g_eg[(size_t)MM * HH];
__device__ float g_o[(size_t)MM * DD];
// fp16 pre-converted GEMM operands
__device__ __half g_xh[(size_t)MM * DD];
__device__ __half g_wqh[(size_t)CONV * DD];
__device__ __half g_wzh[(size_t)DD * DD];
__device__ __half g_woh[(size_t)DD * DD];
__device__ __half g_oh[(size_t)MM * DD];

__device__ __forceinline__ uint32_t smem_u32(const void* p) {
    uint32_t a;
    asm("{ .reg .u64 t; cvta.to.shared.u64 t, %1; cvt.u32.u64 %0, t; }" : "=r"(a) : "l"(p));
    return a;
}

#define LDSM_X4(r0, r1, r2, r3, addr)                                            \
    asm volatile("ldmatrix.sync.aligned.m8n8.x4.shared.b16 {%0,%1,%2,%3}, [%4];" \
                 : "=r"(r0), "=r"(r1), "=r"(r2), "=r"(r3) : "r"(addr))

// ---------------- fused fp16 cvt pre-pass ----------------
#define CV0 (MM * DD / 4)
#define CV1 (CONV * DD / 4)
#define CV2 (DD * DD / 4)
#define CVTOT (CV0 + CV1 + 2 * CV2)

__global__ __launch_bounds__(256) void cvt_all_kernel(const float4* __restrict__ x,
                                                      const float4* __restrict__ wq,
                                                      const float4* __restrict__ wz,
                                                      const float4* __restrict__ wo,
                                                      uint2* __restrict__ xh,
                                                      uint2* __restrict__ wqh,
                                                      uint2* __restrict__ wzh,
                                                      uint2* __restrict__ woh) {
    int i = blockIdx.x * 256 + threadIdx.x;
    const float4* src;
    uint2* dst;
    int off;
    if (i < CV0)                  { src = x;  dst = xh;  off = i; }
    else if (i < CV0 + CV1)       { src = wq; dst = wqh; off = i - CV0; }
    else if (i < CV0 + CV1 + CV2) { src = wz; dst = wzh; off = i - CV0 - CV1; }
    else                          { src = wo; dst = woh; off = i - CV0 - CV1 - CV2; }
    float4 v = src[off];
    __half2 lo = __floats2half2_rn(v.x, v.y);
    __half2 hi = __floats2half2_rn(v.z, v.w);
    dst[off] = make_uint2(*(uint32_t*)&lo, *(uint32_t*)&hi);
}

// ---------------- fp16 tensor-core GEMM, split-N dual output ----------------
// C[M, N1+N2]: columns [0,N1) from W -> Cv (ld N1); [N1,N1+N2) from W2 -> C2 (ld N2).
// 256 threads = 8 warps, block 128x128x32, warp tile 64x32.
// 3-stage cp.async pipeline, SINGLE __syncthreads per k-tile.
#define GBK 32
#define KPH 20
#define TILEW (128 * KPH)
#define BUFW (2 * TILEW)
#define NSTG 3
#define GSMEM3 (NSTG * BUFW * 4)     // 61440 bytes (dynamic)

__global__ __launch_bounds__(256) void hgemm_nt(const __half* __restrict__ A,
                                                const __half* __restrict__ W,
                                                const __half* __restrict__ W2,
                                                void* __restrict__ Cv,
                                                void* __restrict__ C2,
                                                int M, int N1, int N2, int Kd,
                                                int half_out) {
    extern __shared__ uint32_t sm[];
    int tid = threadIdx.x;
    int wid = tid >> 5;
    int lane = tid & 31;
    int bm = blockIdx.y * 128;
    int bnx = blockIdx.x * 128;

    // split-N dispatch
    const __half* Wsel;
    void* Cout;
    int ldn, col0;
    if (bnx < N1) { Wsel = W;  Cout = Cv; ldn = N1; col0 = bnx; }
    else          { Wsel = W2; Cout = C2; ldn = N2; col0 = bnx - N1; }

    int wm = (wid & 1) * 64;
    int wn = (wid >> 1) * 32;
    int g = lane >> 2;
    int tg = lane & 3;

    uint32_t smbase = smem_u32(sm);
    int srow = tid >> 1;
    int shalf = tid & 1;
    const __half* Ap = A + (size_t)(bm + srow) * Kd + shalf * 16;
    const __half* Wp = Wsel + (size_t)(col0 + srow) * Kd + shalf * 16;
    uint32_t rowoff = srow * (KPH * 4) + shalf * 32;

    int lr = lane & 7;
    int lh = (lane >> 3) & 1;
    int lq = lane >> 4;
    uint32_t aBase[4];
#pragma unroll
    for (int mi = 0; mi < 4; mi++)
        aBase[mi] = smbase + (uint32_t)(wm + mi * 16 + lr + lh * 8) * (KPH * 4) + lq * 16;
    uint32_t bBase[2];
#pragma unroll
    for (int p = 0; p < 2; p++)
        bBase[p] = smbase + TILEW * 4 +
                   (uint32_t)(wn + p * 16 + lq * 8 + lr) * (KPH * 4) + lh * 16;

    float acc[4][4][4];
#pragma unroll
    for (int i = 0; i < 4; i++)
#pragma unroll
        for (int j = 0; j < 4; j++)
#pragma unroll
            for (int c = 0; c < 4; c++) acc[i][j][c] = 0.f;

#define STAGE(itx)                                                               \
    {                                                                            \
        uint32_t boff = smbase + (uint32_t)((itx) % NSTG) * (BUFW * 4) + rowoff; \
        int ko = (itx) * GBK;                                                    \
        _Pragma("unroll")                                                        \
        for (int c = 0; c < 2; c++) {                                            \
            asm volatile("cp.async.cg.shared.global [%0], [%1], 16;"             \
                         :: "r"(boff + c * 16), "l"(Ap + ko + c * 8));           \
            asm volatile("cp.async.cg.shared.global [%0], [%1], 16;"             \
                         :: "r"(boff + TILEW * 4 + c * 16), "l"(Wp + ko + c * 8)); \
        }                                                                        \
        asm volatile("cp.async.commit_group;");                                  \
    }

    STAGE(0);
    STAGE(1);

    int ntile = Kd / GBK;
    for (int it = 0; it < ntile; it++) {
        if (it + 1 < ntile) asm volatile("cp.async.wait_group 1;");
        else                asm volatile("cp.async.wait_group 0;");
        __syncthreads();
        // Stage (it+2) AFTER the barrier: its buffer (it+2)%3 == (it-1)%3 was
        // finished by all warps before they passed this barrier.
        if (it + 2 < ntile) STAGE(it + 2);

        uint32_t bsel = (uint32_t)(it % NSTG) * (BUFW * 4);

#pragma unroll
        for (int ks = 0; ks < 2; ks++) {
            uint32_t kofs = bsel + ks * 32;
            uint32_t af[4][4];
            uint32_t bb[2][4];
#pragma unroll
            for (int mi = 0; mi < 4; mi++)
                LDSM_X4(af[mi][0], af[mi][1], af[mi][2], af[mi][3], aBase[mi] + kofs);
#pragma unroll
            for (int p = 0; p < 2; p++)
                LDSM_X4(bb[p][0], bb[p][1], bb[p][2], bb[p][3], bBase[p] + kofs);

#pragma unroll
            for (int mi = 0; mi < 4; mi++)
#pragma unroll
                for (int ni = 0; ni < 4; ni++) {
                    uint32_t b0 = bb[ni >> 1][(ni & 1) * 2];
                    uint32_t b1 = bb[ni >> 1][(ni & 1) * 2 + 1];
                    asm volatile(
                        "mma.sync.aligned.m16n8k16.row.col.f32.f16.f16.f32 "
                        "{%0,%1,%2,%3}, {%4,%5,%6,%7}, {%8,%9}, {%0,%1,%2,%3};"
                        : "+f"(acc[mi][ni][0]), "+f"(acc[mi][ni][1]),
                          "+f"(acc[mi][ni][2]), "+f"(acc[mi][ni][3])
                        : "r"(af[mi][0]), "r"(af[mi][1]), "r"(af[mi][2]), "r"(af[mi][3]),
                          "r"(b0), "r"(b1));
                }
        }
    }
#undef STAGE

    if (half_out) {
        __half* Ch = (__half*)Cout;
#pragma unroll
        for (int mi = 0; mi < 4; mi++) {
#pragma unroll
            for (int ni = 0; ni < 4; ni++) {
                int row0 = bm + wm + mi * 16 + g;
                int col = col0 + wn + ni * 8 + tg * 2;
                *(__half2*)(Ch + (size_t)row0 * ldn + col) =
                    __floats2half2_rn(acc[mi][ni][0], acc[mi][ni][1]);
                *(__half2*)(Ch + (size_t)(row0 + 8) * ldn + col) =
                    __floats2half2_rn(acc[mi][ni][2], acc[mi][ni][3]);
            }
        }
    } else {
        float* C = (float*)Cout;
#pragma unroll
        for (int mi = 0; mi < 4; mi++) {
#pragma unroll
            for (int ni = 0; ni < 4; ni++) {
                int row0 = bm + wm + mi * 16 + g;
                int col = col0 + wn + ni * 8 + tg * 2;
                *(float2*)(C + (size_t)row0 * ldn + col) =
                    make_float2(acc[mi][ni][0], acc[mi][ni][1]);
                *(float2*)(C + (size_t)(row0 + 8) * ldn + col) =
                    make_float2(acc[mi][ni][2], acc[mi][ni][3]);
            }
        }
    }
}

// ---------------- beta/g raw projections, 8 tokens per block ----------------
__global__ __launch_bounds__(256) void att_kernel(const float* __restrict__ x,
                                                  const float* __restrict__ Wb,
                                                  const float* __restrict__ Wa,
                                                  float* __restrict__ att) {
    __shared__ float xs[8][DD];
    int m0 = blockIdx.x * 8;
    int tid = threadIdx.x;
#pragma unroll
    for (int r = 0; r < 8; r++)
        *(float4*)&xs[r][tid * 4] = *(const float4*)(x + (size_t)(m0 + r) * DD + tid * 4);
    __syncthreads();

    int g = tid >> 3;
    int sub = tid & 7;
    const float* w = (g < HH) ? (Wb + (size_t)g * DD) : (Wa + (size_t)(g - HH) * DD);
    float s[8];
#pragma unroll
    for (int r = 0; r < 8; r++) s[r] = 0.f;

    for (int j = sub * 4; j < DD; j += 32) {
        float4 wv = *(const float4*)(w + j);
#pragma unroll
        for (int r = 0; r < 8; r++) {
            float4 xv = *(const float4*)(&xs[r][j]);
            s[r] += wv.x * xv.x + wv.y * xv.y + wv.z * xv.z + wv.w * xv.w;
        }
    }
#pragma unroll
    for (int r = 0; r < 8; r++) {
        s[r] += __shfl_xor_sync(0xffffffffu, s[r], 4);
        s[r] += __shfl_xor_sync(0xffffffffu, s[r], 2);
        s[r] += __shfl_xor_sync(0xffffffffu, s[r], 1);
        if (sub == 0) att[(size_t)(m0 + r) * 32 + g] = s[r];
    }
}

// ---------------- causal depthwise conv (K=4) + SiLU; fp16 input, fp32 math ----------------
__global__ __launch_bounds__(256) void conv_silu_kernel(const __half* __restrict__ mixed,
                                                        const float* __restrict__ cw,
                                                        float* __restrict__ out) {
    int idx = blockIdx.x * 256 + threadIdx.x;
    int c4 = idx % (CONV / 4);
    int mb = idx / (CONV / 4);
    int m0 = mb * 8;
    int t0 = m0 & (TT - 1);
    int c = c4 * 4;

    float4 w0 = *(const float4*)(cw + (size_t)(c + 0) * KK);
    float4 w1 = *(const float4*)(cw + (size_t)(c + 1) * KK);
    float4 w2 = *(const float4*)(cw + (size_t)(c + 2) * KK);
    float4 w3 = *(const float4*)(cw + (size_t)(c + 3) * KK);
    const float* wp0 = (const float*)&w0;
    const float* wp1 = (const float*)&w1;
    const float* wp2 = (const float*)&w2;
    const float* wp3 = (const float*)&w3;

    float4 win[4];
    const float4 zero4 = make_float4(0.f, 0.f, 0.f, 0.f);
#pragma unroll
    for (int s = 0; s < 3; s++) {
        if (t0 - 3 + s >= 0) {
            uint2 hv = *(const uint2*)(mixed + (size_t)(m0 - 3 + s) * CONV + c);
            float2 f0 = __half22float2(*(__half2*)&hv.x);
            float2 f1 = __half22float2(*(__half2*)&hv.y);
            win[s] = make_float4(f0.x, f0.y, f1.x, f1.y);
        } else win[s] = zero4;
    }

#pragma unroll
    for (int tt = 0; tt < 8; tt++) {
        uint2 hv = *(const uint2*)(mixed + (size_t)(m0 + tt) * CONV + c);
        float2 f0 = __half22float2(*(__half2*)&hv.x);
        float2 f1 = __half22float2(*(__half2*)&hv.y);
        win[3] = make_float4(f0.x, f0.y, f1.x, f1.y);
        float a0 = 0.f, a1 = 0.f, a2 = 0.f, a3 = 0.f;
#pragma unroll
        for (int j = 0; j < KK; j++) {
            a0 += wp0[j] * win[j].x;
            a1 += wp1[j] * win[j].y;
            a2 += wp2[j] * win[j].z;
            a3 += wp3[j] * win[j].w;
        }
        float4 r;
        r.x = a0 / (1.f + expf(-a0));
        r.y = a1 / (1.f + expf(-a1));
        r.z = a2 / (1.f + expf(-a2));
        r.w = a3 / (1.f + expf(-a3));
        *(float4*)(out + (size_t)(m0 + tt) * CONV + c) = r;
        win[0] = win[1]; win[1] = win[2]; win[2] = win[3];
    }
}

// ---------------- per-(m,h): l2norm q/k, v*=beta, eg=exp(g) ----------------
__global__ __launch_bounds__(128) void prep_kernel(float* __restrict__ act,
                                                   const float* __restrict__ att,
                                                   const float* __restrict__ dt_bias,
                                                   const float* __restrict__ A_log,
                                                   float* __restrict__ eg) {
    int w = blockIdx.x * 4 + (threadIdx.x >> 5);
    int lane = threadIdx.x & 31;
    int m = w >> 4;
    int h = w & (HH - 1);
    float* base = act + (size_t)m * CONV + h * HD;

    float q0 = base[lane], q1 = base[lane + 32];
    float sq = q0 * q0 + q1 * q1;
#pragma unroll
    for (int o = 16; o; o >>= 1) sq += __shfl_xor_sync(0xffffffffu, sq, o);
    float invq = rsqrtf(sq + 1e-6f) * 0.125f;
    base[lane] = q0 * invq;
    base[lane + 32] = q1 * invq;

    float k0 = base[DD + lane], k1 = base[DD + lane + 32];
    float sk = k0 * k0 + k1 * k1;
#pragma unroll
    for (int o = 16; o; o >>= 1) sk += __shfl_xor_sync(0xffffffffu, sk, o);
    float invk = rsqrtf(sk + 1e-6f);
    base[DD + lane] = k0 * invk;
    base[DD + lane + 32] = k1 * invk;

    float bdot = att[(size_t)m * 32 + h];
    float adot = att[(size_t)m * 32 + HH + h];
    float beta = 1.f / (1.f + expf(-bdot));
    float spin = adot + dt_bias[h];
    float sp = (spin > 20.f) ? spin : log1pf(expf(spin));
    float gg = -expf(A_log[h]) * sp;

    base[2 * DD + lane] *= beta;
    base[2 * DD + lane + 32] *= beta;
    if (lane == 0) eg[(size_t)m * HH + h] = expf(gg);
}

// ---------------- sequential gated scan, smem chunk-staged, batched shuffles ----------------
__global__ __launch_bounds__(64) void scan_kernel(const float* __restrict__ act,
                                                  const float* __restrict__ eg,
                                                  float* __restrict__ o) {
    __shared__ float sq[2][CH][64];
    __shared__ float sk[2][CH][64];
    __shared__ float sv[2][CH][8];
    __shared__ float se[2][CH];

    int bh = blockIdx.x >> 3;
    int cg = blockIdx.x & 7;
    int b = bh >> 4;
    int h = bh & (HH - 1);
    int tid = threadIdx.x;
    int vloc = tid >> 3;
    int part = tid & 7;
    int dbase = part * 8;
    int col = cg * 8 + vloc;

    float S[8];
#pragma unroll
    for (int i = 0; i < 8; i++) S[i] = 0.f;

    const float* abase = act + (size_t)b * TT * CONV + h * HD;
    const float* ebase = eg + (size_t)b * TT * HH + h;
    float* obase = o + (size_t)b * TT * DD + h * HD + col;

    int srow = tid >> 2;
    int sq4 = (tid & 3) * 16;
    uint32_t aq = smem_u32(&sq[0][0][0]);
    uint32_t ak = smem_u32(&sk[0][0][0]);
    uint32_t av = smem_u32(&sv[0][0][0]);
    uint32_t ae = smem_u32(&se[0][0]);

#define SSTAGE(cx)                                                                \
    {                                                                             \
        int bufx = (cx) & 1;                                                      \
        int t0 = (cx) * CH;                                                       \
        const float* gq = abase + (size_t)(t0 + srow) * CONV + sq4;               \
        const float* gk = gq + DD;                                                \
        uint32_t dq = aq + (bufx * CH * 64 + srow * 64 + sq4) * 4;                \
        uint32_t dk = ak + (bufx * CH * 64 + srow * 64 + sq4) * 4;                \
        _Pragma("unroll")                                                         \
        for (int j = 0; j < 4; j++) {                                             \
            asm volatile("cp.async.cg.shared.global [%0], [%1], 16;"              \
                         :: "r"(dq + j * 16), "l"(gq + j * 4));                   \
            asm volatile("cp.async.cg.shared.global [%0], [%1], 16;"              \
                         :: "r"(dk + j * 16), "l"(gk + j * 4));                   \
        }                                                                         \
        if (tid < 32) {                                                           \
            int tv = tid >> 1;                                                    \
            int c2 = (tid & 1) * 4;                                               \
            const float* gv = abase + (size_t)(t0 + tv) * CONV + 2 * DD           \
                              + cg * 8 + c2;                                      \
            uint32_t dv = av + (bufx * CH * 8 + tv * 8 + c2) * 4;                 \
            asm volatile("cp.async.ca.shared.global [%0], [%1], 16;"              \
                         :: "r"(dv), "l"(gv));                                    \
        }                                                                         \
        if (tid < 16) {                                                           \
            const float* ge = ebase + (size_t)(t0 + tid) * HH;                    \
            uint32_t de = ae + (bufx * CH + tid) * 4;                             \
            asm volatile("cp.async.ca.shared.global [%0], [%1], 4;"               \
                         :: "r"(de), "l"(ge));                                    \
        }                                                                         \
        asm volatile("cp.async.commit_group;");                                   \
    }

    SSTAGE(0);

    for (int c = 0; c < NCH; c++) {
        bool more = (c + 1) < NCH;
        if (more) SSTAGE(c + 1);
        if (more) asm volatile("cp.async.wait_group 1;");
        else      asm volatile("cp.async.wait_group 0;");
        __syncthreads();

        int buf = c & 1;
        float dots[CH];
#pragma unroll
        for (int tt = 0; tt < CH; tt++) {
            float qq[8], kk[8];
            *(float4*)(qq + 0) = *(const float4*)(&sq[buf][tt][dbase]);
            *(float4*)(qq + 4) = *(const float4*)(&sq[buf][tt][dbase + 4]);
            *(float4*)(kk + 0) = *(const float4*)(&sk[buf][tt][dbase]);
            *(float4*)(kk + 4) = *(const float4*)(&sk[buf][tt][dbase + 4]);
            float v = sv[buf][tt][vloc];
            float e = se[buf][tt];
            float dot = 0.f;
#pragma unroll
            for (int i = 0; i < 8; i++) {
                S[i] = S[i] * e + kk[i] * v;
                dot += qq[i] * S[i];
            }
            dots[tt] = dot;
        }
#pragma unroll
        for (int tt = 0; tt < CH; tt++) {
            float d = dots[tt];
            d += __shfl_xor_sync(0xffffffffu, d, 1);
            d += __shfl_xor_sync(0xffffffffu, d, 2);
            d += __shfl_xor_sync(0xffffffffu, d, 4);
            if (part == 0) obase[(size_t)(c * CH + tt) * DD] = d;
        }
        __syncthreads();
    }
#undef SSTAGE
}

// ---------------- gated RMSNorm over head dim -> fp16 (z read as fp16) ----------------
__global__ __launch_bounds__(128) void post_kernel(const float* __restrict__ o,
                                                   const __half* __restrict__ z,
                                                   __half* __restrict__ oh) {
    int w = blockIdx.x * 4 + (threadIdx.x >> 5);
    int lane = threadIdx.x & 31;
    int m = w >> 4;
    int h = w & (HH - 1);
    const float* ob = o + (size_t)m * DD + h * HD;
    const __half* zb = z + (size_t)m * DD + h * HD;
    __half* oo = oh + (size_t)m * DD + h * HD;

    float o0 = ob[lane], o1 = ob[lane + 32];
    float s = o0 * o0 + o1 * o1;
#pragma unroll
    for (int off = 16; off; off >>= 1) s += __shfl_xor_sync(0xffffffffu, s, off);
    float r = rsqrtf(s * (1.f / 64.f) + 1e-6f);

    float z0 = __half2float(zb[lane]);
    float z1 = __half2float(zb[lane + 32]);
    float g0 = z0 / (1.f + expf(-z0));
    float g1 = z1 / (1.f + expf(-z1));
    oo[lane]      = __float2half_rn(o0 * r * g0);
    oo[lane + 32] = __float2half_rn(o1 * r * g1);
}

// ---------------- launch ----------------
extern "C" void kernel_launch(void* const* d_in, const int* in_sizes, int n_in,
                              void* d_out, int out_size) {
    const float* x       = (const float*)d_in[0];
    const float* W_qkv   = (const float*)d_in[1];
    const float* conv_w  = (const float*)d_in[2];
    const float* W_z     = (const float*)d_in[3];
    const float* W_b     = (const float*)d_in[4];
    const float* W_a     = (const float*)d_in[5];
    const float* dt_bias = (const float*)d_in[6];
    const float* A_log   = (const float*)d_in[7];
    const float* W_out   = (const float*)d_in[8];
    float* out = (float*)d_out;

    void *p_mixedh, *p_act, *p_zh, *p_att, *p_eg, *p_o;
    void *p_xh, *p_wq, *p_wz, *p_wo, *p_oh;
    cudaGetSymbolAddress(&p_mixedh, g_mixedh);
    cudaGetSymbolAddress(&p_act,   g_act);
    cudaGetSymbolAddress(&p_zh,    g_zh);
    cudaGetSymbolAddress(&p_att,   g_att);
    cudaGetSymbolAddress(&p_eg,    g_eg);
    cudaGetSymbolAddress(&p_o,     g_o);
    cudaGetSymbolAddress(&p_xh,    g_xh);
    cudaGetSymbolAddress(&p_wq,    g_wqh);
    cudaGetSymbolAddress(&p_wz,    g_wzh);
    cudaGetSymbolAddress(&p_wo,    g_woh);
    cudaGetSymbolAddress(&p_oh,    g_oh);
    __half* mixedh = (__half*)p_mixedh;
    float* act   = (float*)p_act;
    __half* zh   = (__half*)p_zh;
    float* att   = (float*)p_att;
    float* egb   = (float*)p_eg;
    float* obuf  = (float*)p_o;
    __half* xh  = (__half*)p_xh;
    __half* wqh = (__half*)p_wq;
    __half* wzh = (__half*)p_wz;
    __half* woh = (__half*)p_wo;
    __half* oh  = (__half*)p_oh;

    cudaFuncSetAttribute(hgemm_nt, cudaFuncAttributeMaxDynamicSharedMemorySize, GSMEM3);

    // 1. fused fp16 pre-conversion
    cvt_all_kernel<<<(CVTOT + 255) / 256, 256>>>(
        (const float4*)x, (const float4*)W_qkv, (const float4*)W_z, (const float4*)W_out,
        (uint2*)xh, (uint2*)wqh, (uint2*)wzh, (uint2*)woh);
    // 2. beta/g raw dots
    att_kernel<<<MM / 8, 256>>>(x, W_b, W_a, att);
    // 3. FUSED qkv + z projection (N = 3072 + 1024), fp16 outputs
    hgemm_nt<<<dim3((CONV + DD) / 128, MM / 128), 256, GSMEM3>>>(
        xh, wqh, wzh, mixedh, zh, MM, CONV, DD, DD, 1);
    // 4. causal depthwise conv + silu
    conv_silu_kernel<<<((MM / 8) * (CONV / 4)) / 256, 256>>>(mixedh, conv_w, act);
    // 5. l2norm q/k, v*beta, eg
    prep_kernel<<<(MM * HH) / 4, 128>>>(act, att, dt_bias, A_log, egb);
    // 6. sequential scan
    scan_kernel<<<BB * HH * 8, 64>>>(act, egb, obuf);
    // 7. gated rmsnorm -> fp16
    post_kernel<<<(MM * HH) / 4, 128>>>(obuf, zh, oh);
    // 8. output projection -> d_out (fp32)
    hgemm_nt<<<dim3(DD / 128, MM / 128), 256, GSMEM3>>>(
        oh, woh, (const __half*)nullptr, out, nullptr, MM, DD, 0, DD, 0);
}